// round 10
// baseline (speedup 1.0000x reference)
#include <cuda_runtime.h>
#include <cuda_bf16.h>
#include <cuda_fp8.h>
#include <cstdint>
#include <cstddef>

// Problem constants
#define B_   2
#define S_   2048
#define H_   2048
#define NH_  16
#define NKV_ 4
#define D_   128
#define MROWS (B_*S_)          // 4096
#define NQKV 3072              // 2048 q | 512 k | 512 v
#define QSCALE 0.08838834764831845f
#define CROSS_DESCALE 1.220703125e-4f   // 2^-13

// ---------------------------------------------------------------------------
// PTX helpers
// ---------------------------------------------------------------------------
__device__ __forceinline__ uint32_t smem_to_u32(const void* p) {
    uint32_t a;
    asm("{ .reg .u64 t; cvta.to.shared.u64 t, %1; cvt.u32.u64 %0, t; }" : "=r"(a) : "l"(p));
    return a;
}
__device__ __forceinline__ void ldsm4(uint32_t* r, uint32_t addr) {
    asm volatile("ldmatrix.sync.aligned.m8n8.x4.shared.b16 {%0,%1,%2,%3}, [%4];"
        : "=r"(r[0]), "=r"(r[1]), "=r"(r[2]), "=r"(r[3]) : "r"(addr));
}
__device__ __forceinline__ void ldsm4t(uint32_t* r, uint32_t addr) {
    asm volatile("ldmatrix.sync.aligned.m8n8.x4.trans.shared.b16 {%0,%1,%2,%3}, [%4];"
        : "=r"(r[0]), "=r"(r[1]), "=r"(r[2]), "=r"(r[3]) : "r"(addr));
}
__device__ __forceinline__ void mma_bf16(float* d, const uint32_t* a, uint32_t b0, uint32_t b1) {
    asm volatile("mma.sync.aligned.m16n8k16.row.col.f32.bf16.bf16.f32 "
        "{%0,%1,%2,%3}, {%4,%5,%6,%7}, {%8,%9}, {%0,%1,%2,%3};"
        : "+f"(d[0]), "+f"(d[1]), "+f"(d[2]), "+f"(d[3])
        : "r"(a[0]), "r"(a[1]), "r"(a[2]), "r"(a[3]), "r"(b0), "r"(b1));
}
__device__ __forceinline__ void mma_fp8(float* d, const uint32_t* a, uint32_t b0, uint32_t b1) {
    asm volatile("mma.sync.aligned.m16n8k32.row.col.f32.e4m3.e4m3.f32 "
        "{%0,%1,%2,%3}, {%4,%5,%6,%7}, {%8,%9}, {%0,%1,%2,%3};"
        : "+f"(d[0]), "+f"(d[1]), "+f"(d[2]), "+f"(d[3])
        : "r"(a[0]), "r"(a[1]), "r"(a[2]), "r"(a[3]), "r"(b0), "r"(b1));
}
__device__ __forceinline__ void cpasync16(uint32_t saddr, const void* g) {
    asm volatile("cp.async.cg.shared.global [%0], [%1], 16;" :: "r"(saddr), "l"(g));
}
#define CP_COMMIT() asm volatile("cp.async.commit_group;" ::: "memory")
#define CP_WAIT(n)  asm volatile("cp.async.wait_group %0;" :: "n"(n) : "memory")

__device__ __forceinline__ void split2pack(float a, float b, uint32_t& hi, uint32_t& lo) {
    __nv_bfloat16 ah = __float2bfloat16_rn(a);
    __nv_bfloat16 bh = __float2bfloat16_rn(b);
    __nv_bfloat16 al = __float2bfloat16_rn(a - __bfloat162float(ah));
    __nv_bfloat16 bl = __float2bfloat16_rn(b - __bfloat162float(bh));
    hi = (uint32_t)(*(uint16_t*)&ah) | ((uint32_t)(*(uint16_t*)&bh) << 16);
    lo = (uint32_t)(*(uint16_t*)&al) | ((uint32_t)(*(uint16_t*)&bl) << 16);
}
__device__ __forceinline__ uint8_t f2e4m3(float f) {
    __nv_fp8_e4m3 v(f);
    return *reinterpret_cast<uint8_t*>(&v);
}
// fp8 tile swizzle: 128 rows x 32B; macro-row m=r>>2 (128B), slot s=(r&3)*2+u
__device__ __forceinline__ uint32_t f8off(int r, int u) {
    int m = r >> 2;
    int s = (((r & 3) * 2 + u) ^ (m & 7));
    return (uint32_t)(m * 128 + s * 16);
}

// ---------------------------------------------------------------------------
// Scratch (device globals)
// ---------------------------------------------------------------------------
__device__ float g_qkv[(size_t)MROWS * NQKV];        // fp32 q|k|v projections

__device__ __nv_bfloat16 g_xhi [(size_t)MROWS * H_];
__device__ uint8_t       g_xlo8[(size_t)MROWS * H_];
__device__ uint8_t       g_xhi8[(size_t)MROWS * H_];
__device__ __nv_bfloat16 g_ahi [(size_t)MROWS * H_]; // attention out
__device__ uint8_t       g_alo8[(size_t)MROWS * H_];
__device__ uint8_t       g_ahi8[(size_t)MROWS * H_];
__device__ __nv_bfloat16 g_wh  [(size_t)NQKV * H_];  // [3072,2048] Wq|Wkv transposed
__device__ uint8_t       g_wh8 [(size_t)NQKV * H_];  // fp8(w*16)
__device__ uint8_t       g_wl8 [(size_t)NQKV * H_];  // fp8(lo*8192)
__device__ __nv_bfloat16 g_woh [(size_t)H_ * H_];
__device__ uint8_t       g_woh8[(size_t)H_ * H_];
__device__ uint8_t       g_wol8[(size_t)H_ * H_];
// attention operands (bf16 hi/lo)
__device__ __nv_bfloat16 g_qhi[(size_t)MROWS * (NH_*D_)];
__device__ __nv_bfloat16 g_qlo[(size_t)MROWS * (NH_*D_)];
__device__ __nv_bfloat16 g_khi[(size_t)MROWS * (NKV_*D_)];
__device__ __nv_bfloat16 g_klo[(size_t)MROWS * (NKV_*D_)];
__device__ __nv_bfloat16 g_vhi[(size_t)MROWS * (NKV_*D_)];
__device__ __nv_bfloat16 g_vlo[(size_t)MROWS * (NKV_*D_)];

// ---------------------------------------------------------------------------
// split fp32 -> bf16 hi + fp8(lo*512) + fp8(val). 8 elems/thread.
// ---------------------------------------------------------------------------
__global__ void splitx_kernel(const float* __restrict__ in,
                              __nv_bfloat16* __restrict__ hi,
                              uint8_t* __restrict__ lo8,
                              uint8_t* __restrict__ hi8, int n8)
{
    int idx = blockIdx.x * blockDim.x + threadIdx.x;
    if (idx >= n8) return;
    union { __nv_bfloat16 b[8]; uint4 u; } uh;
    union { uint8_t b[8]; uint2 u; } ul8, uh8;
    const float4* in4 = (const float4*)in;
#pragma unroll
    for (int q = 0; q < 2; q++) {
        float4 v = in4[idx * 2 + q];
        float f[4] = {v.x, v.y, v.z, v.w};
#pragma unroll
        for (int i = 0; i < 4; i++) {
            __nv_bfloat16 h = __float2bfloat16_rn(f[i]);
            uh.b[q * 4 + i] = h;
            ul8.b[q * 4 + i] = f2e4m3((f[i] - __bfloat162float(h)) * 512.0f);
            uh8.b[q * 4 + i] = f2e4m3(f[i]);
        }
    }
    ((uint4*)hi)[idx] = uh.u;
    ((uint2*)lo8)[idx] = ul8.u;
    ((uint2*)hi8)[idx] = uh8.u;
}

// ---------------------------------------------------------------------------
// split + transpose: W[K,N] fp32 -> Thi bf16[N,K] + fp8(w*16) + fp8(lo*8192).
// ---------------------------------------------------------------------------
__global__ void splitT_kernel(const float* __restrict__ W,
                              __nv_bfloat16* __restrict__ Thi,
                              uint8_t* __restrict__ Thi8,
                              uint8_t* __restrict__ Tlo8, int K, int N)
{
    __shared__ float s[32][33];
    int tx = threadIdx.x, ty = threadIdx.y;           // (32, 8)
    int n0 = blockIdx.x * 32, k0 = blockIdx.y * 32;
#pragma unroll
    for (int i = 0; i < 4; i++) {
        int k = k0 + ty + i * 8;
        s[ty + i * 8][tx] = W[(size_t)k * N + n0 + tx];
    }
    __syncthreads();
#pragma unroll
    for (int i = 0; i < 4; i++) {
        int n = n0 + ty + i * 8;
        float v = s[tx][ty + i * 8];
        __nv_bfloat16 h = __float2bfloat16_rn(v);
        size_t o = (size_t)n * K + k0 + tx;
        Thi[o]  = h;
        Thi8[o] = f2e4m3(v * 16.0f);
        Tlo8[o] = f2e4m3((v - __bfloat162float(h)) * 8192.0f);
    }
}

// ---------------------------------------------------------------------------
// GEMM: bf16 hi*hi + fp8 cross terms (a_lo*b_hi + a_hi*b_lo, shared 2^13 scale).
// 128x128 CTA tile, BK=32, 8 warps, 4-stage cp.async (R6-proven protocol).
// ---------------------------------------------------------------------------
#define STAGE_BYTES  32768
#define ST_AHI  0
#define ST_BHI  8192
#define ST_ALO8 16384
#define ST_AHI8 20480
#define ST_BHI8 24576
#define ST_BLO8 28672
#define NSTAGE 4
#define GEMM_SMEM_BYTES (NSTAGE * STAGE_BYTES)   // 131072

__global__ __launch_bounds__(256)
void gemm_mma(const __nv_bfloat16* __restrict__ Ahi, const uint8_t* __restrict__ Alo8,
              const uint8_t* __restrict__ Ahi8,
              const __nv_bfloat16* __restrict__ Bhi, const uint8_t* __restrict__ Bhi8,
              const uint8_t* __restrict__ Blo8,
              float* __restrict__ C, int M, int N, int K)
{
    extern __shared__ char smem[];
    const uint32_t sbase = smem_to_u32(smem);
    const int tid  = threadIdx.x;
    const int wid  = tid >> 5;
    const int lane = tid & 31;
    const int br = blockIdx.y * 128;
    const int bc = blockIdx.x * 128;
    const int wr = wid & 3;
    const int wc = wid >> 2;

    const int nchunks = K >> 5;

    // bf16 tile slots (2 units/thread, 64B rows, proven swizzle)
    int r0u = (2 * tid) >> 2, u0 = (2 * tid) & 3;
    int r1u = (2 * tid + 1) >> 2, u1 = (2 * tid + 1) & 3;
    uint32_t so0 = (uint32_t)(r0u * 64 + (u0 ^ ((r0u >> 1) & 3)) * 16);
    uint32_t so1 = (uint32_t)(r1u * 64 + (u1 ^ ((r1u >> 1) & 3)) * 16);
    // fp8 tile slot (1 unit/thread)
    int rf = tid >> 1, uf = tid & 1;
    uint32_t f8so = f8off(rf, uf);

    float acc[2][8][4], cac[2][8][4];
#pragma unroll
    for (int i = 0; i < 2; i++)
#pragma unroll
        for (int j = 0; j < 8; j++)
#pragma unroll
            for (int q = 0; q < 4; q++) { acc[i][j][q] = 0.f; cac[i][j][q] = 0.f; }

    const int arow0 = wr * 32 + (lane & 15);
    const int arow1 = arow0 + 16;
    const int khalf = lane >> 4;

    auto issue_loads = [&](int c, int stage) {
        uint32_t sb = sbase + stage * STAGE_BYTES;
        const __nv_bfloat16* pAh = Ahi + (size_t)br * K + c * 32;
        const __nv_bfloat16* pBh = Bhi + (size_t)bc * K + c * 32;
        size_t g0 = (size_t)r0u * K + u0 * 8;
        size_t g1 = (size_t)r1u * K + u1 * 8;
        cpasync16(sb + ST_AHI + so0, pAh + g0);
        cpasync16(sb + ST_AHI + so1, pAh + g1);
        cpasync16(sb + ST_BHI + so0, pBh + g0);
        cpasync16(sb + ST_BHI + so1, pBh + g1);
        size_t ga = (size_t)(br + rf) * K + c * 32 + uf * 16;
        size_t gb = (size_t)(bc + rf) * K + c * 32 + uf * 16;
        cpasync16(sb + ST_ALO8 + f8so, Alo8 + ga);
        cpasync16(sb + ST_AHI8 + f8so, Ahi8 + ga);
        cpasync16(sb + ST_BHI8 + f8so, Bhi8 + gb);
        cpasync16(sb + ST_BLO8 + f8so, Blo8 + gb);
    };

    // prologue: chunks 0..2 into stages 0..2 (groups 0..2)
#pragma unroll
    for (int c = 0; c < 3; c++) {
        if (c < nchunks) issue_loads(c, c);
        CP_COMMIT();
    }

    for (int c = 0; c < nchunks; c++) {
        CP_WAIT(2);                 // group c complete
        __syncthreads();            // stage (c-1)&3 drained by all warps
        if (c + 3 < nchunks) issue_loads(c + 3, (c + 3) & 3);
        CP_COMMIT();                // unconditional: group index tracks chunk index

        uint32_t sA = sbase + (c & 3) * STAGE_BYTES;

        // ---- bf16 hi*hi ----
#pragma unroll
        for (int kk = 0; kk < 2; kk++) {
            uint32_t ah[2][4];
#pragma unroll
            for (int mt = 0; mt < 2; mt++) {
                int row = (mt ? arow1 : arow0);
                int cc  = (kk * 2 + khalf) ^ ((row >> 1) & 3);
                ldsm4(ah[mt], sA + ST_AHI + (uint32_t)(row * 64 + cc * 16));
            }
#pragma unroll
            for (int ng = 0; ng < 4; ng++) {
                int row = wc * 64 + ng * 16 + (lane & 15);
                int cc  = (kk * 2 + khalf) ^ ((row >> 1) & 3);
                uint32_t bh[4];
                ldsm4(bh, sA + ST_BHI + (uint32_t)(row * 64 + cc * 16));
#pragma unroll
                for (int hf = 0; hf < 2; hf++) {
                    int j = 2 * ng + hf;
                    mma_bf16(acc[0][j], ah[0], bh[hf], bh[2 + hf]);
                    mma_bf16(acc[1][j], ah[1], bh[hf], bh[2 + hf]);
                }
            }
        }

        // ---- fp8 cross terms (single k32) ----
        {
            uint32_t a8l[2][4], a8h[2][4];
#pragma unroll
            for (int mt = 0; mt < 2; mt++) {
                int row = wr * 32 + mt * 16 + (lane & 15);
                uint32_t off = f8off(row, khalf);
                ldsm4(a8l[mt], sA + ST_ALO8 + off);
                ldsm4(a8h[mt], sA + ST_AHI8 + off);
            }
#pragma unroll
            for (int ng = 0; ng < 4; ng++) {
                int row = wc * 64 + ng * 16 + (lane & 15);
                uint32_t off = f8off(row, khalf);
                uint32_t b8h[4], b8l[4];
                ldsm4(b8h, sA + ST_BHI8 + off);
                ldsm4(b8l, sA + ST_BLO8 + off);
#pragma unroll
                for (int hf = 0; hf < 2; hf++) {
                    int j = 2 * ng + hf;
                    mma_fp8(cac[0][j], a8l[0], b8h[hf], b8h[2 + hf]);
                    mma_fp8(cac[0][j], a8h[0], b8l[hf], b8l[2 + hf]);
                    mma_fp8(cac[1][j], a8l[1], b8h[hf], b8h[2 + hf]);
                    mma_fp8(cac[1][j], a8h[1], b8l[hf], b8l[2 + hf]);
                }
            }
        }
    }

#pragma unroll
    for (int mt = 0; mt < 2; mt++) {
        int row = br + wr * 32 + mt * 16 + (lane >> 2);
#pragma unroll
        for (int j = 0; j < 8; j++) {
            int col = bc + wc * 64 + j * 8 + (lane & 3) * 2;
            *(float2*)(C + (size_t)row * N + col) =
                make_float2(acc[mt][j][0] + cac[mt][j][0] * CROSS_DESCALE,
                            acc[mt][j][1] + cac[mt][j][1] * CROSS_DESCALE);
            *(float2*)(C + (size_t)(row + 8) * N + col) =
                make_float2(acc[mt][j][2] + cac[mt][j][2] * CROSS_DESCALE,
                            acc[mt][j][3] + cac[mt][j][3] * CROSS_DESCALE);
        }
    }
}

// ---------------------------------------------------------------------------
// RoPE -> bf16 hi/lo. Q variant folds 1/sqrt(D) scale. (unchanged)
// ---------------------------------------------------------------------------
__global__ void rope_bf16_kernel(const float* __restrict__ buf, int nheads, int ld,
                                 const float* __restrict__ cosT,
                                 const float* __restrict__ sinT,
                                 __nv_bfloat16* __restrict__ ohi,
                                 __nv_bfloat16* __restrict__ olo,
                                 float scale, int total)
{
    int idx = blockIdx.x * blockDim.x + threadIdx.x;
    if (idx >= total) return;
    int d2 = idx & 31;
    int h  = (idx >> 5) % nheads;
    int bs = idx / (32 * nheads);
    int s  = bs & (S_ - 1);
    int d  = d2 * 2;
    const float* p = buf + (size_t)bs * ld + h * D_;
    float x1a = p[d],      x1b = p[d + 1];
    float x2a = p[d + 64], x2b = p[d + 65];
    float ca = cosT[s * D_ + d], cb = cosT[s * D_ + d + 1];
    float sa = sinT[s * D_ + d], sb = sinT[s * D_ + d + 1];
    float o1a = (x1a * ca - x2a * sa) * scale;
    float o1b = (x1b * cb - x2b * sb) * scale;
    float o2a = (x2a * ca + x1a * sa) * scale;
    float o2b = (x2b * cb + x1b * sb) * scale;
    uint32_t h1, l1, h2, l2;
    split2pack(o1a, o1b, h1, l1);
    split2pack(o2a, o2b, h2, l2);
    size_t ob = (size_t)bs * (nheads * D_) + h * D_;
    *(uint32_t*)(ohi + ob + d)      = h1;
    *(uint32_t*)(olo + ob + d)      = l1;
    *(uint32_t*)(ohi + ob + d + 64) = h2;
    *(uint32_t*)(olo + ob + d + 64) = l2;
}

// V split: g_qkv cols [2560,3072) -> vhi/vlo [4096][512] (unchanged)
__global__ void vsplit_kernel(const float* __restrict__ qkv,
                              __nv_bfloat16* __restrict__ vhi,
                              __nv_bfloat16* __restrict__ vlo)
{
    int idx = blockIdx.x * blockDim.x + threadIdx.x;   // 4096*64
    int u8 = idx & 63;
    int r  = idx >> 6;
    const float* src = qkv + (size_t)r * NQKV + 2560 + u8 * 8;
    union { __nv_bfloat16 b[8]; uint4 u; } uh, ul;
#pragma unroll
    for (int q = 0; q < 2; q++) {
        float4 v = *(const float4*)(src + q * 4);
        float f[4] = {v.x, v.y, v.z, v.w};
#pragma unroll
        for (int i = 0; i < 4; i++) {
            __nv_bfloat16 hh = __float2bfloat16_rn(f[i]);
            uh.b[q * 4 + i] = hh;
            ul.b[q * 4 + i] = __float2bfloat16_rn(f[i] - __bfloat162float(hh));
        }
    }
    *(uint4*)(vhi + (size_t)r * 512 + u8 * 8) = uh.u;
    *(uint4*)(vlo + (size_t)r * 512 + u8 * 8) = ul.u;
}

// ---------------------------------------------------------------------------
// Tensor-core flash attention (R9-proven), epilogue now emits bf16 hi + fp8 planes.
// ---------------------------------------------------------------------------
#define A_SQH 0
#define A_SQL 32768
#define A_SKV 65536
#define A_STAGE 65536
#define ATT_SMEM_BYTES (65536 + 2*65536)   // 196608

__global__ __launch_bounds__(256, 1)
void attn_tc(const __nv_bfloat16* __restrict__ qhi, const __nv_bfloat16* __restrict__ qlo,
             const __nv_bfloat16* __restrict__ khi, const __nv_bfloat16* __restrict__ klo,
             const __nv_bfloat16* __restrict__ vhi, const __nv_bfloat16* __restrict__ vlo,
             __nv_bfloat16* __restrict__ Ohi, uint8_t* __restrict__ Olo8,
             uint8_t* __restrict__ Ohi8,
             const int* __restrict__ seqlen)
{
    extern __shared__ char smem[];
    const uint32_t sb = smem_to_u32(smem);
    const int tid  = threadIdx.x;
    const int wid  = tid >> 5;
    const int lane = tid & 31;
    const int bh = blockIdx.x;                 // 0..31
    const int qt = 15 - blockIdx.y;            // heavy tiles first
    const int b   = bh >> 4;
    const int h   = bh & 15;
    const int kvh = h >> 2;
    const int q0  = qt * 128;
    const int len = seqlen[b];

    // ---- load Q tile (hi/lo) ----
    {
        const __nv_bfloat16* qh = qhi + (size_t)(b * S_ + q0) * (NH_*D_) + h * D_;
        const __nv_bfloat16* ql = qlo + (size_t)(b * S_ + q0) * (NH_*D_) + h * D_;
#pragma unroll
        for (int i = 0; i < 8; i++) {
            int g = i * 256 + tid;
            int r = g >> 4, u = g & 15;
            uint32_t so = (uint32_t)(r * 256 + ((u ^ (r & 7)) * 16));
            size_t go = (size_t)r * (NH_*D_) + u * 8;
            cpasync16(sb + A_SQH + so, qh + go);
            cpasync16(sb + A_SQL + so, ql + go);
        }
    }

    const int e  = min(q0 + 128, len);
    const int nt = (e + 63) >> 6;

    auto load_kv = [&](int t, int stage) {
        uint32_t st = sb + A_SKV + stage * A_STAGE;
        size_t base = (size_t)(b * S_ + t * 64) * (NKV_*D_) + kvh * D_;
#pragma unroll
        for (int i = 0; i < 4; i++) {
            int g = i * 256 + tid;
            int r = g >> 4, u = g & 15;
            uint32_t so = (uint32_t)(r * 256 + ((u ^ (r & 7)) * 16));
            size_t go = base + (size_t)r * (NKV_*D_) + u * 8;
            cpasync16(st + so,         khi + go);
            cpasync16(st + 16384 + so, klo + go);
            cpasync16(st + 32768 + so, vhi + go);
            cpasync16(st + 49152 + so, vlo + go);
        }
    };

    load_kv(0, 0);
    CP_COMMIT();

    float out[16][4];
#pragma unroll
    for (int j = 0; j < 16; j++)
#pragma unroll
        for (int q = 0; q < 4; q++) out[j][q] = 0.f;
    float m0 = -1e30f, m1 = -1e30f, l0 = 0.f, l1 = 0.f;

    const int wrow = q0 + wid * 16;

    for (int t = 0; t < nt; t++) {
        if (t + 1 < nt) { load_kv(t + 1, (t + 1) & 1); CP_COMMIT(); CP_WAIT(1); }
        else            { CP_WAIT(0); }
        __syncthreads();

        const int k0 = t * 64;
        if (k0 <= wrow + 15) {
            uint32_t sK = sb + A_SKV + (t & 1) * A_STAGE;
            uint32_t sV = sK + 32768;

            float s[8][4];
#pragma unroll
            for (int j = 0; j < 8; j++)
#pragma unroll
                for (int q = 0; q < 4; q++) s[j][q] = 0.f;

#pragma unroll
            for (int kk = 0; kk < 8; kk++) {
                int ar = wid * 16 + (lane & 15);
                int au = 2 * kk + (lane >> 4);
                uint32_t aso = (uint32_t)(ar * 256 + ((au ^ (ar & 7)) * 16));
                uint32_t ah[4], al[4];
                ldsm4(ah, sb + A_SQH + aso);
                ldsm4(al, sb + A_SQL + aso);
#pragma unroll
                for (int ng = 0; ng < 4; ng++) {
                    int br = ng * 16 + (lane & 15);
                    uint32_t bso = (uint32_t)(br * 256 + ((au ^ (br & 7)) * 16));
                    uint32_t bhf[4], blf[4];
                    ldsm4(bhf, sK + bso);
                    ldsm4(blf, sK + 16384 + bso);
#pragma unroll
                    for (int hf = 0; hf < 2; hf++) {
                        int j = 2 * ng + hf;
                        mma_bf16(s[j], ah, bhf[hf], bhf[2 + hf]);
                        mma_bf16(s[j], ah, blf[hf], blf[2 + hf]);
                        mma_bf16(s[j], al, bhf[hf], bhf[2 + hf]);
                    }
                }
            }

            const int qr0 = wrow + (lane >> 2);
            bool fullvalid = (k0 + 63 <= wrow) && (k0 + 63 < len);
            if (!fullvalid) {
#pragma unroll
                for (int j = 0; j < 8; j++) {
                    int kgb = k0 + j * 8 + (lane & 3) * 2;
#pragma unroll
                    for (int q = 0; q < 4; q++) {
                        int kg = kgb + (q & 1);
                        int qg = qr0 + ((q >> 1) << 3);
                        if (kg > qg || kg >= len) s[j][q] = -1e30f;
                    }
                }
            }

            float mx0 = -1e30f, mx1 = -1e30f;
#pragma unroll
            for (int j = 0; j < 8; j++) {
                mx0 = fmaxf(mx0, fmaxf(s[j][0], s[j][1]));
                mx1 = fmaxf(mx1, fmaxf(s[j][2], s[j][3]));
            }
#pragma unroll
            for (int off = 1; off <= 2; off <<= 1) {
                mx0 = fmaxf(mx0, __shfl_xor_sync(0xffffffffu, mx0, off));
                mx1 = fmaxf(mx1, __shfl_xor_sync(0xffffffffu, mx1, off));
            }
            float nm0 = fmaxf(m0, mx0), nm1 = fmaxf(m1, mx1);
            float sc0 = __expf(m0 - nm0), sc1 = __expf(m1 - nm1);
            m0 = nm0; m1 = nm1;
            float sum0 = 0.f, sum1 = 0.f;
#pragma unroll
            for (int j = 0; j < 8; j++) {
                s[j][0] = __expf(s[j][0] - nm0);
                s[j][1] = __expf(s[j][1] - nm0);
                s[j][2] = __expf(s[j][2] - nm1);
                s[j][3] = __expf(s[j][3] - nm1);
                sum0 += s[j][0] + s[j][1];
                sum1 += s[j][2] + s[j][3];
            }
#pragma unroll
            for (int off = 1; off <= 2; off <<= 1) {
                sum0 += __shfl_xor_sync(0xffffffffu, sum0, off);
                sum1 += __shfl_xor_sync(0xffffffffu, sum1, off);
            }
            l0 = l0 * sc0 + sum0;
            l1 = l1 * sc1 + sum1;
#pragma unroll
            for (int j = 0; j < 16; j++) {
                out[j][0] *= sc0; out[j][1] *= sc0;
                out[j][2] *= sc1; out[j][3] *= sc1;
            }

#pragma unroll
            for (int jk = 0; jk < 4; jk++) {
                uint32_t ph[4], pl[4];
                split2pack(s[2*jk][0],   s[2*jk][1],   ph[0], pl[0]);
                split2pack(s[2*jk][2],   s[2*jk][3],   ph[1], pl[1]);
                split2pack(s[2*jk+1][0], s[2*jk+1][1], ph[2], pl[2]);
                split2pack(s[2*jk+1][2], s[2*jk+1][3], ph[3], pl[3]);
#pragma unroll
                for (int gn = 0; gn < 8; gn++) {
                    int vr = jk * 16 + (lane & 15);
                    int vu = 2 * gn + (lane >> 4);
                    uint32_t vso = (uint32_t)(vr * 256 + ((vu ^ (vr & 7)) * 16));
                    uint32_t vh4[4], vl4[4];
                    ldsm4t(vh4, sV + vso);
                    ldsm4t(vl4, sV + 16384 + vso);
#pragma unroll
                    for (int hf = 0; hf < 2; hf++) {
                        int jn = 2 * gn + hf;
                        mma_bf16(out[jn], ph, vh4[2*hf], vh4[2*hf + 1]);
                        mma_bf16(out[jn], pl, vh4[2*hf], vh4[2*hf + 1]);
                        mma_bf16(out[jn], ph, vl4[2*hf], vl4[2*hf + 1]);
                    }
                }
            }
        }
        __syncthreads();
    }

    // ---- epilogue: normalize, emit bf16 hi + fp8(lo*512) + fp8(val) ----
    float i0 = 1.0f / l0, i1 = 1.0f / l1;
    size_t ro0 = (size_t)(b * S_ + wrow + (lane >> 2)) * (NH_*D_) + h * D_;
    size_t ro1 = ro0 + (size_t)8 * (NH_*D_);
#pragma unroll
    for (int jn = 0; jn < 16; jn++) {
        int col = jn * 8 + (lane & 3) * 2;
        {
            float o0 = out[jn][0] * i0, o1 = out[jn][1] * i0;
            __nv_bfloat16 h0 = __float2bfloat16_rn(o0), h1 = __float2bfloat16_rn(o1);
            *(uint32_t*)(Ohi + ro0 + col) =
                (uint32_t)(*(uint16_t*)&h0) | ((uint32_t)(*(uint16_t*)&h1) << 16);
            *(uint16_t*)(Olo8 + ro0 + col) =
                (uint16_t)f2e4m3((o0 - __bfloat162float(h0)) * 512.0f) |
                ((uint16_t)f2e4m3((o1 - __bfloat162float(h1)) * 512.0f) << 8);
            *(uint16_t*)(Ohi8 + ro0 + col) =
                (uint16_t)f2e4m3(o0) | ((uint16_t)f2e4m3(o1) << 8);
        }
        {
            float o0 = out[jn][2] * i1, o1 = out[jn][3] * i1;
            __nv_bfloat16 h0 = __float2bfloat16_rn(o0), h1 = __float2bfloat16_rn(o1);
            *(uint32_t*)(Ohi + ro1 + col) =
                (uint32_t)(*(uint16_t*)&h0) | ((uint32_t)(*(uint16_t*)&h1) << 16);
            *(uint16_t*)(Olo8 + ro1 + col) =
                (uint16_t)f2e4m3((o0 - __bfloat162float(h0)) * 512.0f) |
                ((uint16_t)f2e4m3((o1 - __bfloat162float(h1)) * 512.0f) << 8);
            *(uint16_t*)(Ohi8 + ro1 + col) =
                (uint16_t)f2e4m3(o0) | ((uint16_t)f2e4m3(o1) << 8);
        }
    }
}

// ---------------------------------------------------------------------------
// Launch
// ---------------------------------------------------------------------------
extern "C" void kernel_launch(void* const* d_in, const int* in_sizes, int n_in,
                              void* d_out, int out_size)
{
    const float* x    = (const float*)d_in[0];
    const int*   seq  = (const int*)  d_in[1];
    const float* fcos = (const float*)d_in[2];
    const float* fsin = (const float*)d_in[3];
    const float* Wq   = (const float*)d_in[4];
    const float* Wkv  = (const float*)d_in[5];
    const float* Wo   = (const float*)d_in[6];
    float* out = (float*)d_out;

    float *qkv;
    cudaGetSymbolAddress((void**)&qkv, g_qkv);
    __nv_bfloat16 *xhi, *ahi, *wh, *woh;
    uint8_t *xlo8, *xhi8, *alo8, *ahi8, *wh8, *wl8, *woh8, *wol8;
    __nv_bfloat16 *qhi, *qlo, *khi, *klo, *vhi, *vlo;
    cudaGetSymbolAddress((void**)&xhi,  g_xhi);
    cudaGetSymbolAddress((void**)&xlo8, g_xlo8);
    cudaGetSymbolAddress((void**)&xhi8, g_xhi8);
    cudaGetSymbolAddress((void**)&ahi,  g_ahi);
    cudaGetSymbolAddress((void**)&alo8, g_alo8);
    cudaGetSymbolAddress((void**)&ahi8, g_ahi8);
    cudaGetSymbolAddress((void**)&wh,   g_wh);
    cudaGetSymbolAddress((void**)&wh8,  g_wh8);
    cudaGetSymbolAddress((void**)&wl8,  g_wl8);
    cudaGetSymbolAddress((void**)&woh,  g_woh);
    cudaGetSymbolAddress((void**)&woh8, g_woh8);
    cudaGetSymbolAddress((void**)&wol8, g_wol8);
    cudaGetSymbolAddress((void**)&qhi, g_qhi);
    cudaGetSymbolAddress((void**)&qlo, g_qlo);
    cudaGetSymbolAddress((void**)&khi, g_khi);
    cudaGetSymbolAddress((void**)&klo, g_klo);
    cudaGetSymbolAddress((void**)&vhi, g_vhi);
    cudaGetSymbolAddress((void**)&vlo, g_vlo);

    cudaFuncSetAttribute(gemm_mma, cudaFuncAttributeMaxDynamicSharedMemorySize, GEMM_SMEM_BYTES);
    cudaFuncSetAttribute(attn_tc,  cudaFuncAttributeMaxDynamicSharedMemorySize, ATT_SMEM_BYTES);

    dim3 blk(256);

    // 0) precision-split preprocessing
    {
        int n8 = MROWS * H_ / 8;
        splitx_kernel<<<(n8 + 255) / 256, 256>>>(x, xhi, xlo8, xhi8, n8);
        dim3 tb(32, 8);
        splitT_kernel<<<dim3((NH_*D_)/32,    H_/32), tb>>>(Wq,  wh,                      wh8,                      wl8,                      H_, NH_*D_);
        splitT_kernel<<<dim3((2*NKV_*D_)/32, H_/32), tb>>>(Wkv, wh  + (size_t)2048 * H_, wh8 + (size_t)2048 * H_,  wl8 + (size_t)2048 * H_,  H_, 2*NKV_*D_);
        splitT_kernel<<<dim3(H_/32,          H_/32), tb>>>(Wo,  woh, woh8, wol8, H_, H_);
    }

    // 1) fused QKV projection
    gemm_mma<<<dim3(24, 32), blk, GEMM_SMEM_BYTES>>>(xhi, xlo8, xhi8, wh, wh8, wl8, qkv, MROWS, NQKV, H_);

    // 2) RoPE -> bf16 hi/lo (Q folds softmax scale); V split
    {
        int tq = MROWS * NH_ * 32;
        int tk = MROWS * NKV_ * 32;
        rope_bf16_kernel<<<(tq + 255) / 256, 256>>>(qkv,        NH_,  NQKV, fcos, fsin, qhi, qlo, QSCALE, tq);
        rope_bf16_kernel<<<(tk + 255) / 256, 256>>>(qkv + 2048, NKV_, NQKV, fcos, fsin, khi, klo, 1.0f,   tk);
        int tv = MROWS * 64;
        vsplit_kernel<<<(tv + 255) / 256, 256>>>(qkv, vhi, vlo);
    }

    // 3) attention (tensor-core, split-bf16, emits bf16 hi + fp8 planes)
    attn_tc<<<dim3(32, 16), blk, ATT_SMEM_BYTES>>>(qhi, qlo, khi, klo, vhi, vlo, ahi, alo8, ahi8, seq);

    // 4) output projection
    gemm_mma<<<dim3(16, 32), blk, GEMM_SMEM_BYTES>>>(ahi, alo8, ahi8, woh, woh8, wol8, out, MROWS, H_, H_);
}

// round 11
// speedup vs baseline: 1.5864x; 1.5864x over previous
#include <cuda_runtime.h>
#include <cuda_bf16.h>
#include <cuda_fp16.h>
#include <cstdint>
#include <cstddef>

// Problem constants
#define B_   2
#define S_   2048
#define H_   2048
#define NH_  16
#define NKV_ 4
#define D_   128
#define MROWS (B_*S_)          // 4096
#define NQKV 3072              // 2048 q | 512 k | 512 v
#define QSCALE 0.08838834764831845f

// ---------------------------------------------------------------------------
// PTX helpers (sm_100-safe: mma.sync / ldmatrix / cp.async only)
// ---------------------------------------------------------------------------
__device__ __forceinline__ uint32_t smem_to_u32(const void* p) {
    uint32_t a;
    asm("{ .reg .u64 t; cvta.to.shared.u64 t, %1; cvt.u32.u64 %0, t; }" : "=r"(a) : "l"(p));
    return a;
}
__device__ __forceinline__ void ldsm4(uint32_t* r, uint32_t addr) {
    asm volatile("ldmatrix.sync.aligned.m8n8.x4.shared.b16 {%0,%1,%2,%3}, [%4];"
        : "=r"(r[0]), "=r"(r[1]), "=r"(r[2]), "=r"(r[3]) : "r"(addr));
}
__device__ __forceinline__ void ldsm4t(uint32_t* r, uint32_t addr) {
    asm volatile("ldmatrix.sync.aligned.m8n8.x4.trans.shared.b16 {%0,%1,%2,%3}, [%4];"
        : "=r"(r[0]), "=r"(r[1]), "=r"(r[2]), "=r"(r[3]) : "r"(addr));
}
__device__ __forceinline__ void mma_bf16(float* d, const uint32_t* a, uint32_t b0, uint32_t b1) {
    asm volatile("mma.sync.aligned.m16n8k16.row.col.f32.bf16.bf16.f32 "
        "{%0,%1,%2,%3}, {%4,%5,%6,%7}, {%8,%9}, {%0,%1,%2,%3};"
        : "+f"(d[0]), "+f"(d[1]), "+f"(d[2]), "+f"(d[3])
        : "r"(a[0]), "r"(a[1]), "r"(a[2]), "r"(a[3]), "r"(b0), "r"(b1));
}
__device__ __forceinline__ void mma_fp16(float* d, const uint32_t* a, uint32_t b0, uint32_t b1) {
    asm volatile("mma.sync.aligned.m16n8k16.row.col.f32.f16.f16.f32 "
        "{%0,%1,%2,%3}, {%4,%5,%6,%7}, {%8,%9}, {%0,%1,%2,%3};"
        : "+f"(d[0]), "+f"(d[1]), "+f"(d[2]), "+f"(d[3])
        : "r"(a[0]), "r"(a[1]), "r"(a[2]), "r"(a[3]), "r"(b0), "r"(b1));
}
__device__ __forceinline__ void cpasync16(uint32_t saddr, const void* g) {
    asm volatile("cp.async.cg.shared.global [%0], [%1], 16;" :: "r"(saddr), "l"(g));
}
#define CP_COMMIT() asm volatile("cp.async.commit_group;" ::: "memory")
#define CP_WAIT(n)  asm volatile("cp.async.wait_group %0;" :: "n"(n) : "memory")

__device__ __forceinline__ void split2pack(float a, float b, uint32_t& hi, uint32_t& lo) {
    __nv_bfloat16 ah = __float2bfloat16_rn(a);
    __nv_bfloat16 bh = __float2bfloat16_rn(b);
    __nv_bfloat16 al = __float2bfloat16_rn(a - __bfloat162float(ah));
    __nv_bfloat16 bl = __float2bfloat16_rn(b - __bfloat162float(bh));
    hi = (uint32_t)(*(uint16_t*)&ah) | ((uint32_t)(*(uint16_t*)&bh) << 16);
    lo = (uint32_t)(*(uint16_t*)&al) | ((uint32_t)(*(uint16_t*)&bl) << 16);
}
__device__ __forceinline__ void split2pack_h(float a, float b, uint32_t& hi, uint32_t& lo) {
    __half ah = __float2half_rn(a);
    __half bh = __float2half_rn(b);
    __half al = __float2half_rn(a - __half2float(ah));
    __half bl = __float2half_rn(b - __half2float(bh));
    hi = (uint32_t)(*(uint16_t*)&ah) | ((uint32_t)(*(uint16_t*)&bh) << 16);
    lo = (uint32_t)(*(uint16_t*)&al) | ((uint32_t)(*(uint16_t*)&bl) << 16);
}

// ---------------------------------------------------------------------------
// Scratch (device globals)
// ---------------------------------------------------------------------------
__device__ float g_qkv[(size_t)MROWS * NQKV];        // fp32 q|k|v projections

__device__ __half g_xhi[(size_t)MROWS * H_];         // fp16 split of x
__device__ __half g_xlo[(size_t)MROWS * H_];
__device__ __half g_ahi[(size_t)MROWS * H_];         // fp16 split of attention out
__device__ __half g_alo[(size_t)MROWS * H_];
__device__ __half g_wh [(size_t)NQKV * H_];          // fp16 Wq|Wkv transposed [3072,2048]
__device__ __half g_woh[(size_t)H_ * H_];            // fp16 Wo transposed
// attention operands (bf16 hi/lo) — unchanged
__device__ __nv_bfloat16 g_qhi[(size_t)MROWS * (NH_*D_)];
__device__ __nv_bfloat16 g_qlo[(size_t)MROWS * (NH_*D_)];
__device__ __nv_bfloat16 g_khi[(size_t)MROWS * (NKV_*D_)];
__device__ __nv_bfloat16 g_klo[(size_t)MROWS * (NKV_*D_)];
__device__ __nv_bfloat16 g_vhi[(size_t)MROWS * (NKV_*D_)];
__device__ __nv_bfloat16 g_vlo[(size_t)MROWS * (NKV_*D_)];

// ---------------------------------------------------------------------------
// split fp32 -> fp16 hi/lo (row-major, same layout). 8 elems/thread.
// ---------------------------------------------------------------------------
__global__ void splitx_kernel(const float* __restrict__ in,
                              __half* __restrict__ hi,
                              __half* __restrict__ lo, int n8)
{
    int idx = blockIdx.x * blockDim.x + threadIdx.x;
    if (idx >= n8) return;
    union { __half b[8]; uint4 u; } uh, ul;
    const float4* in4 = (const float4*)in;
#pragma unroll
    for (int q = 0; q < 2; q++) {
        float4 v = in4[idx * 2 + q];
        float f[4] = {v.x, v.y, v.z, v.w};
#pragma unroll
        for (int i = 0; i < 4; i++) {
            __half h = __float2half_rn(f[i]);
            uh.b[q * 4 + i] = h;
            ul.b[q * 4 + i] = __float2half_rn(f[i] - __half2float(h));
        }
    }
    ((uint4*)hi)[idx] = uh.u;
    ((uint4*)lo)[idx] = ul.u;
}

// ---------------------------------------------------------------------------
// transpose + fp16: W[K,N] fp32 -> T[N,K] fp16. 32x32 smem tiles.
// ---------------------------------------------------------------------------
__global__ void splitT_kernel(const float* __restrict__ W,
                              __half* __restrict__ T, int K, int N)
{
    __shared__ float s[32][33];
    int tx = threadIdx.x, ty = threadIdx.y;           // (32, 8)
    int n0 = blockIdx.x * 32, k0 = blockIdx.y * 32;
#pragma unroll
    for (int i = 0; i < 4; i++) {
        int k = k0 + ty + i * 8;
        s[ty + i * 8][tx] = W[(size_t)k * N + n0 + tx];
    }
    __syncthreads();
#pragma unroll
    for (int i = 0; i < 4; i++) {
        int n = n0 + ty + i * 8;
        T[(size_t)n * K + k0 + tx] = __float2half_rn(s[tx][ty + i * 8]);
    }
}

// ---------------------------------------------------------------------------
// fp16 asymmetric-split GEMM: C = (Ahi + Alo)[M,K] @ B[N,K]^T  (2 MMA passes)
// 128x128 CTA tile, BK=32, 8 warps, 2-stage cp.async (R9-proven protocol),
// 2 CTAs/SM (48KB smem, regs capped via per-ng B consumption).
// ---------------------------------------------------------------------------
#define TILE_BYTES   8192
#define STAGE_BYTES  (3 * TILE_BYTES)        // Ahi | Alo | B
#define ST_AHI 0
#define ST_ALO 8192
#define ST_B   16384
#define GEMM_SMEM_BYTES (2 * STAGE_BYTES)    // 49152 -> 2 CTAs/SM

__global__ __launch_bounds__(256, 2)
void gemm_mma(const __half* __restrict__ Ahi, const __half* __restrict__ Alo,
              const __half* __restrict__ B,
              float* __restrict__ C, int M, int N, int K)
{
    extern __shared__ char smem[];
    const uint32_t sbase = smem_to_u32(smem);
    const int tid  = threadIdx.x;
    const int wid  = tid >> 5;
    const int lane = tid & 31;
    const int br = blockIdx.y * 128;
    const int bc = blockIdx.x * 128;
    const int wr = wid & 3;
    const int wc = wid >> 2;

    const int nchunks = K >> 5;

    int r0u = (2 * tid) >> 2, u0 = (2 * tid) & 3;
    int r1u = (2 * tid + 1) >> 2, u1 = (2 * tid + 1) & 3;
    uint32_t so0 = (uint32_t)(r0u * 64 + (u0 ^ ((r0u >> 1) & 3)) * 16);
    uint32_t so1 = (uint32_t)(r1u * 64 + (u1 ^ ((r1u >> 1) & 3)) * 16);

    float acc[2][8][4];
#pragma unroll
    for (int i = 0; i < 2; i++)
#pragma unroll
        for (int j = 0; j < 8; j++)
#pragma unroll
            for (int q = 0; q < 4; q++) acc[i][j][q] = 0.f;

    const int arow0 = wr * 32 + (lane & 15);
    const int arow1 = arow0 + 16;
    const int khalf = lane >> 4;

    auto issue_loads = [&](int c, int stage) {
        uint32_t sb = sbase + stage * STAGE_BYTES;
        const __half* pAh = Ahi + (size_t)br * K + c * 32;
        const __half* pAl = Alo + (size_t)br * K + c * 32;
        const __half* pB  = B   + (size_t)bc * K + c * 32;
        size_t g0 = (size_t)r0u * K + u0 * 8;
        size_t g1 = (size_t)r1u * K + u1 * 8;
        cpasync16(sb + ST_AHI + so0, pAh + g0);
        cpasync16(sb + ST_AHI + so1, pAh + g1);
        cpasync16(sb + ST_ALO + so0, pAl + g0);
        cpasync16(sb + ST_ALO + so1, pAl + g1);
        cpasync16(sb + ST_B + so0,   pB + g0);
        cpasync16(sb + ST_B + so1,   pB + g1);
    };

    issue_loads(0, 0);
    CP_COMMIT();

    for (int c = 0; c < nchunks; c++) {
        if (c + 1 < nchunks) {
            issue_loads(c + 1, (c + 1) & 1);
            CP_COMMIT();
            CP_WAIT(1);
        } else {
            CP_WAIT(0);
        }
        __syncthreads();

        uint32_t sA = sbase + (c & 1) * STAGE_BYTES;

#pragma unroll
        for (int kk = 0; kk < 2; kk++) {
            uint32_t ah[2][4], al[2][4];
#pragma unroll
            for (int mt = 0; mt < 2; mt++) {
                int row = (mt ? arow1 : arow0);
                int cc  = (kk * 2 + khalf) ^ ((row >> 1) & 3);
                uint32_t ad = sA + (uint32_t)(row * 64 + cc * 16);
                ldsm4(ah[mt], ad + ST_AHI);
                ldsm4(al[mt], ad + ST_ALO);
            }
            // per-ng B load + immediate consume
#pragma unroll
            for (int ng = 0; ng < 4; ng++) {
                int row = wc * 64 + ng * 16 + (lane & 15);
                int cc  = (kk * 2 + khalf) ^ ((row >> 1) & 3);
                uint32_t bh[4];
                ldsm4(bh, sA + ST_B + (uint32_t)(row * 64 + cc * 16));
#pragma unroll
                for (int hf = 0; hf < 2; hf++) {
                    int j = 2 * ng + hf;
                    mma_fp16(acc[0][j], ah[0], bh[hf], bh[2 + hf]);
                    mma_fp16(acc[0][j], al[0], bh[hf], bh[2 + hf]);
                    mma_fp16(acc[1][j], ah[1], bh[hf], bh[2 + hf]);
                    mma_fp16(acc[1][j], al[1], bh[hf], bh[2 + hf]);
                }
            }
        }
        __syncthreads();
    }

#pragma unroll
    for (int mt = 0; mt < 2; mt++) {
        int row = br + wr * 32 + mt * 16 + (lane >> 2);
#pragma unroll
        for (int j = 0; j < 8; j++) {
            int col = bc + wc * 64 + j * 8 + (lane & 3) * 2;
            *(float2*)(C + (size_t)row * N + col) =
                make_float2(acc[mt][j][0], acc[mt][j][1]);
            *(float2*)(C + (size_t)(row + 8) * N + col) =
                make_float2(acc[mt][j][2], acc[mt][j][3]);
        }
    }
}

// ---------------------------------------------------------------------------
// RoPE -> bf16 hi/lo. Q variant folds 1/sqrt(D) scale. (unchanged)
// ---------------------------------------------------------------------------
__global__ void rope_bf16_kernel(const float* __restrict__ buf, int nheads, int ld,
                                 const float* __restrict__ cosT,
                                 const float* __restrict__ sinT,
                                 __nv_bfloat16* __restrict__ ohi,
                                 __nv_bfloat16* __restrict__ olo,
                                 float scale, int total)
{
    int idx = blockIdx.x * blockDim.x + threadIdx.x;
    if (idx >= total) return;
    int d2 = idx & 31;
    int h  = (idx >> 5) % nheads;
    int bs = idx / (32 * nheads);
    int s  = bs & (S_ - 1);
    int d  = d2 * 2;
    const float* p = buf + (size_t)bs * ld + h * D_;
    float x1a = p[d],      x1b = p[d + 1];
    float x2a = p[d + 64], x2b = p[d + 65];
    float ca = cosT[s * D_ + d], cb = cosT[s * D_ + d + 1];
    float sa = sinT[s * D_ + d], sb = sinT[s * D_ + d + 1];
    float o1a = (x1a * ca - x2a * sa) * scale;
    float o1b = (x1b * cb - x2b * sb) * scale;
    float o2a = (x2a * ca + x1a * sa) * scale;
    float o2b = (x2b * cb + x1b * sb) * scale;
    uint32_t h1, l1, h2, l2;
    split2pack(o1a, o1b, h1, l1);
    split2pack(o2a, o2b, h2, l2);
    size_t ob = (size_t)bs * (nheads * D_) + h * D_;
    *(uint32_t*)(ohi + ob + d)      = h1;
    *(uint32_t*)(olo + ob + d)      = l1;
    *(uint32_t*)(ohi + ob + d + 64) = h2;
    *(uint32_t*)(olo + ob + d + 64) = l2;
}

// V split: g_qkv cols [2560,3072) -> vhi/vlo [4096][512] (unchanged)
__global__ void vsplit_kernel(const float* __restrict__ qkv,
                              __nv_bfloat16* __restrict__ vhi,
                              __nv_bfloat16* __restrict__ vlo)
{
    int idx = blockIdx.x * blockDim.x + threadIdx.x;   // 4096*64
    int u8 = idx & 63;
    int r  = idx >> 6;
    const float* src = qkv + (size_t)r * NQKV + 2560 + u8 * 8;
    union { __nv_bfloat16 b[8]; uint4 u; } uh, ul;
#pragma unroll
    for (int q = 0; q < 2; q++) {
        float4 v = *(const float4*)(src + q * 4);
        float f[4] = {v.x, v.y, v.z, v.w};
#pragma unroll
        for (int i = 0; i < 4; i++) {
            __nv_bfloat16 hh = __float2bfloat16_rn(f[i]);
            uh.b[q * 4 + i] = hh;
            ul.b[q * 4 + i] = __float2bfloat16_rn(f[i] - __bfloat162float(hh));
        }
    }
    *(uint4*)(vhi + (size_t)r * 512 + u8 * 8) = uh.u;
    *(uint4*)(vlo + (size_t)r * 512 + u8 * 8) = ul.u;
}

// ---------------------------------------------------------------------------
// Tensor-core flash attention, split-bf16 (R9-proven); epilogue emits fp16 hi/lo.
// ---------------------------------------------------------------------------
#define A_SQH 0
#define A_SQL 32768
#define A_SKV 65536
#define A_STAGE 65536
#define ATT_SMEM_BYTES (65536 + 2*65536)   // 196608

__global__ __launch_bounds__(256, 1)
void attn_tc(const __nv_bfloat16* __restrict__ qhi, const __nv_bfloat16* __restrict__ qlo,
             const __nv_bfloat16* __restrict__ khi, const __nv_bfloat16* __restrict__ klo,
             const __nv_bfloat16* __restrict__ vhi, const __nv_bfloat16* __restrict__ vlo,
             __half* __restrict__ Ohi, __half* __restrict__ Olo,
             const int* __restrict__ seqlen)
{
    extern __shared__ char smem[];
    const uint32_t sb = smem_to_u32(smem);
    const int tid  = threadIdx.x;
    const int wid  = tid >> 5;
    const int lane = tid & 31;
    const int bh = blockIdx.x;                 // 0..31
    const int qt = 15 - blockIdx.y;            // heavy tiles first
    const int b   = bh >> 4;
    const int h   = bh & 15;
    const int kvh = h >> 2;
    const int q0  = qt * 128;
    const int len = seqlen[b];

    // ---- load Q tile (hi/lo) ----
    {
        const __nv_bfloat16* qh = qhi + (size_t)(b * S_ + q0) * (NH_*D_) + h * D_;
        const __nv_bfloat16* ql = qlo + (size_t)(b * S_ + q0) * (NH_*D_) + h * D_;
#pragma unroll
        for (int i = 0; i < 8; i++) {
            int g = i * 256 + tid;
            int r = g >> 4, u = g & 15;
            uint32_t so = (uint32_t)(r * 256 + ((u ^ (r & 7)) * 16));
            size_t go = (size_t)r * (NH_*D_) + u * 8;
            cpasync16(sb + A_SQH + so, qh + go);
            cpasync16(sb + A_SQL + so, ql + go);
        }
    }

    const int e  = min(q0 + 128, len);
    const int nt = (e + 63) >> 6;

    auto load_kv = [&](int t, int stage) {
        uint32_t st = sb + A_SKV + stage * A_STAGE;
        size_t base = (size_t)(b * S_ + t * 64) * (NKV_*D_) + kvh * D_;
#pragma unroll
        for (int i = 0; i < 4; i++) {
            int g = i * 256 + tid;
            int r = g >> 4, u = g & 15;
            uint32_t so = (uint32_t)(r * 256 + ((u ^ (r & 7)) * 16));
            size_t go = base + (size_t)r * (NKV_*D_) + u * 8;
            cpasync16(st + so,         khi + go);
            cpasync16(st + 16384 + so, klo + go);
            cpasync16(st + 32768 + so, vhi + go);
            cpasync16(st + 49152 + so, vlo + go);
        }
    };

    load_kv(0, 0);
    CP_COMMIT();

    float out[16][4];
#pragma unroll
    for (int j = 0; j < 16; j++)
#pragma unroll
        for (int q = 0; q < 4; q++) out[j][q] = 0.f;
    float m0 = -1e30f, m1 = -1e30f, l0 = 0.f, l1 = 0.f;

    const int wrow = q0 + wid * 16;

    for (int t = 0; t < nt; t++) {
        if (t + 1 < nt) { load_kv(t + 1, (t + 1) & 1); CP_COMMIT(); CP_WAIT(1); }
        else            { CP_WAIT(0); }
        __syncthreads();

        const int k0 = t * 64;
        if (k0 <= wrow + 15) {
            uint32_t sK = sb + A_SKV + (t & 1) * A_STAGE;
            uint32_t sV = sK + 32768;

            float s[8][4];
#pragma unroll
            for (int j = 0; j < 8; j++)
#pragma unroll
                for (int q = 0; q < 4; q++) s[j][q] = 0.f;

#pragma unroll
            for (int kk = 0; kk < 8; kk++) {
                int ar = wid * 16 + (lane & 15);
                int au = 2 * kk + (lane >> 4);
                uint32_t aso = (uint32_t)(ar * 256 + ((au ^ (ar & 7)) * 16));
                uint32_t ah[4], al[4];
                ldsm4(ah, sb + A_SQH + aso);
                ldsm4(al, sb + A_SQL + aso);
#pragma unroll
                for (int ng = 0; ng < 4; ng++) {
                    int br = ng * 16 + (lane & 15);
                    uint32_t bso = (uint32_t)(br * 256 + ((au ^ (br & 7)) * 16));
                    uint32_t bhf[4], blf[4];
                    ldsm4(bhf, sK + bso);
                    ldsm4(blf, sK + 16384 + bso);
#pragma unroll
                    for (int hf = 0; hf < 2; hf++) {
                        int j = 2 * ng + hf;
                        mma_bf16(s[j], ah, bhf[hf], bhf[2 + hf]);
                        mma_bf16(s[j], ah, blf[hf], blf[2 + hf]);
                        mma_bf16(s[j], al, bhf[hf], bhf[2 + hf]);
                    }
                }
            }

            const int qr0 = wrow + (lane >> 2);
            bool fullvalid = (k0 + 63 <= wrow) && (k0 + 63 < len);
            if (!fullvalid) {
#pragma unroll
                for (int j = 0; j < 8; j++) {
                    int kgb = k0 + j * 8 + (lane & 3) * 2;
#pragma unroll
                    for (int q = 0; q < 4; q++) {
                        int kg = kgb + (q & 1);
                        int qg = qr0 + ((q >> 1) << 3);
                        if (kg > qg || kg >= len) s[j][q] = -1e30f;
                    }
                }
            }

            float mx0 = -1e30f, mx1 = -1e30f;
#pragma unroll
            for (int j = 0; j < 8; j++) {
                mx0 = fmaxf(mx0, fmaxf(s[j][0], s[j][1]));
                mx1 = fmaxf(mx1, fmaxf(s[j][2], s[j][3]));
            }
#pragma unroll
            for (int off = 1; off <= 2; off <<= 1) {
                mx0 = fmaxf(mx0, __shfl_xor_sync(0xffffffffu, mx0, off));
                mx1 = fmaxf(mx1, __shfl_xor_sync(0xffffffffu, mx1, off));
            }
            float nm0 = fmaxf(m0, mx0), nm1 = fmaxf(m1, mx1);
            float sc0 = __expf(m0 - nm0), sc1 = __expf(m1 - nm1);
            m0 = nm0; m1 = nm1;
            float sum0 = 0.f, sum1 = 0.f;
#pragma unroll
            for (int j = 0; j < 8; j++) {
                s[j][0] = __expf(s[j][0] - nm0);
                s[j][1] = __expf(s[j][1] - nm0);
                s[j][2] = __expf(s[j][2] - nm1);
                s[j][3] = __expf(s[j][3] - nm1);
                sum0 += s[j][0] + s[j][1];
                sum1 += s[j][2] + s[j][3];
            }
#pragma unroll
            for (int off = 1; off <= 2; off <<= 1) {
                sum0 += __shfl_xor_sync(0xffffffffu, sum0, off);
                sum1 += __shfl_xor_sync(0xffffffffu, sum1, off);
            }
            l0 = l0 * sc0 + sum0;
            l1 = l1 * sc1 + sum1;
#pragma unroll
            for (int j = 0; j < 16; j++) {
                out[j][0] *= sc0; out[j][1] *= sc0;
                out[j][2] *= sc1; out[j][3] *= sc1;
            }

#pragma unroll
            for (int jk = 0; jk < 4; jk++) {
                uint32_t ph[4], pl[4];
                split2pack(s[2*jk][0],   s[2*jk][1],   ph[0], pl[0]);
                split2pack(s[2*jk][2],   s[2*jk][3],   ph[1], pl[1]);
                split2pack(s[2*jk+1][0], s[2*jk+1][1], ph[2], pl[2]);
                split2pack(s[2*jk+1][2], s[2*jk+1][3], ph[3], pl[3]);
#pragma unroll
                for (int gn = 0; gn < 8; gn++) {
                    int vr = jk * 16 + (lane & 15);
                    int vu = 2 * gn + (lane >> 4);
                    uint32_t vso = (uint32_t)(vr * 256 + ((vu ^ (vr & 7)) * 16));
                    uint32_t vh4[4], vl4[4];
                    ldsm4t(vh4, sV + vso);
                    ldsm4t(vl4, sV + 16384 + vso);
#pragma unroll
                    for (int hf = 0; hf < 2; hf++) {
                        int jn = 2 * gn + hf;
                        mma_bf16(out[jn], ph, vh4[2*hf], vh4[2*hf + 1]);
                        mma_bf16(out[jn], pl, vh4[2*hf], vh4[2*hf + 1]);
                        mma_bf16(out[jn], ph, vl4[2*hf], vl4[2*hf + 1]);
                    }
                }
            }
        }
        __syncthreads();
    }

    // ---- epilogue: normalize, split to fp16 hi/lo, store ----
    float i0 = 1.0f / l0, i1 = 1.0f / l1;
    size_t ro0 = (size_t)(b * S_ + wrow + (lane >> 2)) * (NH_*D_) + h * D_;
    size_t ro1 = ro0 + (size_t)8 * (NH_*D_);
#pragma unroll
    for (int jn = 0; jn < 16; jn++) {
        int col = jn * 8 + (lane & 3) * 2;
        uint32_t hh, ll;
        split2pack_h(out[jn][0] * i0, out[jn][1] * i0, hh, ll);
        *(uint32_t*)(Ohi + ro0 + col) = hh;
        *(uint32_t*)(Olo + ro0 + col) = ll;
        split2pack_h(out[jn][2] * i1, out[jn][3] * i1, hh, ll);
        *(uint32_t*)(Ohi + ro1 + col) = hh;
        *(uint32_t*)(Olo + ro1 + col) = ll;
    }
}

// ---------------------------------------------------------------------------
// Launch
// ---------------------------------------------------------------------------
extern "C" void kernel_launch(void* const* d_in, const int* in_sizes, int n_in,
                              void* d_out, int out_size)
{
    const float* x    = (const float*)d_in[0];
    const int*   seq  = (const int*)  d_in[1];
    const float* fcos = (const float*)d_in[2];
    const float* fsin = (const float*)d_in[3];
    const float* Wq   = (const float*)d_in[4];
    const float* Wkv  = (const float*)d_in[5];
    const float* Wo   = (const float*)d_in[6];
    float* out = (float*)d_out;

    float *qkv;
    cudaGetSymbolAddress((void**)&qkv, g_qkv);
    __half *xhi, *xlo, *ahi, *alo, *wh, *woh;
    __nv_bfloat16 *qhi, *qlo, *khi, *klo, *vhi, *vlo;
    cudaGetSymbolAddress((void**)&xhi, g_xhi);
    cudaGetSymbolAddress((void**)&xlo, g_xlo);
    cudaGetSymbolAddress((void**)&ahi, g_ahi);
    cudaGetSymbolAddress((void**)&alo, g_alo);
    cudaGetSymbolAddress((void**)&wh,  g_wh);
    cudaGetSymbolAddress((void**)&woh, g_woh);
    cudaGetSymbolAddress((void**)&qhi, g_qhi);
    cudaGetSymbolAddress((void**)&qlo, g_qlo);
    cudaGetSymbolAddress((void**)&khi, g_khi);
    cudaGetSymbolAddress((void**)&klo, g_klo);
    cudaGetSymbolAddress((void**)&vhi, g_vhi);
    cudaGetSymbolAddress((void**)&vlo, g_vlo);

    cudaFuncSetAttribute(gemm_mma, cudaFuncAttributeMaxDynamicSharedMemorySize, GEMM_SMEM_BYTES);
    cudaFuncSetAttribute(attn_tc,  cudaFuncAttributeMaxDynamicSharedMemorySize, ATT_SMEM_BYTES);

    dim3 blk(256);

    // 0) preprocessing: x -> fp16 hi/lo; W -> fp16 transposed
    {
        int n8 = MROWS * H_ / 8;
        splitx_kernel<<<(n8 + 255) / 256, 256>>>(x, xhi, xlo, n8);
        dim3 tb(32, 8);
        splitT_kernel<<<dim3((NH_*D_)/32,    H_/32), tb>>>(Wq,  wh,                     H_, NH_*D_);
        splitT_kernel<<<dim3((2*NKV_*D_)/32, H_/32), tb>>>(Wkv, wh + (size_t)2048 * H_, H_, 2*NKV_*D_);
        splitT_kernel<<<dim3(H_/32,          H_/32), tb>>>(Wo,  woh, H_, H_);
    }

    // 1) fused QKV projection (fp16 asymmetric split, 2 passes)
    gemm_mma<<<dim3(24, 32), blk, GEMM_SMEM_BYTES>>>(xhi, xlo, wh, qkv, MROWS, NQKV, H_);

    // 2) RoPE -> bf16 hi/lo (Q folds softmax scale); V split
    {
        int tq = MROWS * NH_ * 32;
        int tk = MROWS * NKV_ * 32;
        rope_bf16_kernel<<<(tq + 255) / 256, 256>>>(qkv,        NH_,  NQKV, fcos, fsin, qhi, qlo, QSCALE, tq);
        rope_bf16_kernel<<<(tk + 255) / 256, 256>>>(qkv + 2048, NKV_, NQKV, fcos, fsin, khi, klo, 1.0f,   tk);
        int tv = MROWS * 64;
        vsplit_kernel<<<(tv + 255) / 256, 256>>>(qkv, vhi, vlo);
    }

    // 3) attention (tensor-core, split-bf16, emits fp16 hi/lo)
    attn_tc<<<dim3(32, 16), blk, ATT_SMEM_BYTES>>>(qhi, qlo, khi, klo, vhi, vlo, ahi, alo, seq);

    // 4) output projection
    gemm_mma<<<dim3(16, 32), blk, GEMM_SMEM_BYTES>>>(ahi, alo, woh, out, MROWS, H_, H_);
}

// round 12
// speedup vs baseline: 2.2828x; 1.4390x over previous
#include <cuda_runtime.h>
#include <cuda_bf16.h>
#include <cuda_fp16.h>
#include <cstdint>
#include <cstddef>

// Problem constants
#define B_   2
#define S_   2048
#define H_   2048
#define NH_  16
#define NKV_ 4
#define D_   128
#define MROWS (B_*S_)          // 4096
#define NQKV 3072              // 2048 q | 512 k | 512 v
#define QSCALE 0.08838834764831845f

// ---------------------------------------------------------------------------
// PTX helpers (sm_100-safe: mma.sync / ldmatrix / cp.async only)
// ---------------------------------------------------------------------------
__device__ __forceinline__ uint32_t smem_to_u32(const void* p) {
    uint32_t a;
    asm("{ .reg .u64 t; cvta.to.shared.u64 t, %1; cvt.u32.u64 %0, t; }" : "=r"(a) : "l"(p));
    return a;
}
__device__ __forceinline__ void ldsm4(uint32_t* r, uint32_t addr) {
    asm volatile("ldmatrix.sync.aligned.m8n8.x4.shared.b16 {%0,%1,%2,%3}, [%4];"
        : "=r"(r[0]), "=r"(r[1]), "=r"(r[2]), "=r"(r[3]) : "r"(addr));
}
__device__ __forceinline__ void ldsm4t(uint32_t* r, uint32_t addr) {
    asm volatile("ldmatrix.sync.aligned.m8n8.x4.trans.shared.b16 {%0,%1,%2,%3}, [%4];"
        : "=r"(r[0]), "=r"(r[1]), "=r"(r[2]), "=r"(r[3]) : "r"(addr));
}
__device__ __forceinline__ void mma_bf16(float* d, const uint32_t* a, uint32_t b0, uint32_t b1) {
    asm volatile("mma.sync.aligned.m16n8k16.row.col.f32.bf16.bf16.f32 "
        "{%0,%1,%2,%3}, {%4,%5,%6,%7}, {%8,%9}, {%0,%1,%2,%3};"
        : "+f"(d[0]), "+f"(d[1]), "+f"(d[2]), "+f"(d[3])
        : "r"(a[0]), "r"(a[1]), "r"(a[2]), "r"(a[3]), "r"(b0), "r"(b1));
}
__device__ __forceinline__ void mma_fp16(float* d, const uint32_t* a, uint32_t b0, uint32_t b1) {
    asm volatile("mma.sync.aligned.m16n8k16.row.col.f32.f16.f16.f32 "
        "{%0,%1,%2,%3}, {%4,%5,%6,%7}, {%8,%9}, {%0,%1,%2,%3};"
        : "+f"(d[0]), "+f"(d[1]), "+f"(d[2]), "+f"(d[3])
        : "r"(a[0]), "r"(a[1]), "r"(a[2]), "r"(a[3]), "r"(b0), "r"(b1));
}
__device__ __forceinline__ void cpasync16(uint32_t saddr, const void* g) {
    asm volatile("cp.async.cg.shared.global [%0], [%1], 16;" :: "r"(saddr), "l"(g));
}
#define CP_COMMIT() asm volatile("cp.async.commit_group;" ::: "memory")
#define CP_WAIT(n)  asm volatile("cp.async.wait_group %0;" :: "n"(n) : "memory")

__device__ __forceinline__ void split2pack(float a, float b, uint32_t& hi, uint32_t& lo) {
    __nv_bfloat16 ah = __float2bfloat16_rn(a);
    __nv_bfloat16 bh = __float2bfloat16_rn(b);
    __nv_bfloat16 al = __float2bfloat16_rn(a - __bfloat162float(ah));
    __nv_bfloat16 bl = __float2bfloat16_rn(b - __bfloat162float(bh));
    hi = (uint32_t)(*(uint16_t*)&ah) | ((uint32_t)(*(uint16_t*)&bh) << 16);
    lo = (uint32_t)(*(uint16_t*)&al) | ((uint32_t)(*(uint16_t*)&bl) << 16);
}
__device__ __forceinline__ uint32_t pack2h(float a, float b) {
    __half ah = __float2half_rn(a);
    __half bh = __float2half_rn(b);
    return (uint32_t)(*(uint16_t*)&ah) | ((uint32_t)(*(uint16_t*)&bh) << 16);
}

// ---------------------------------------------------------------------------
// Scratch (device globals)
// ---------------------------------------------------------------------------
__device__ float g_qkv[(size_t)MROWS * NQKV];        // fp32 q|k|v projections

__device__ __half g_x16[(size_t)MROWS * H_];         // fp16 x
__device__ __half g_a16[(size_t)MROWS * H_];         // fp16 attention out
__device__ __half g_wh [(size_t)NQKV * H_];          // fp16 Wq|Wkv transposed [3072,2048]
__device__ __half g_woh[(size_t)H_ * H_];            // fp16 Wo transposed
// attention operands (bf16 hi/lo) — unchanged
__device__ __nv_bfloat16 g_qhi[(size_t)MROWS * (NH_*D_)];
__device__ __nv_bfloat16 g_qlo[(size_t)MROWS * (NH_*D_)];
__device__ __nv_bfloat16 g_khi[(size_t)MROWS * (NKV_*D_)];
__device__ __nv_bfloat16 g_klo[(size_t)MROWS * (NKV_*D_)];
__device__ __nv_bfloat16 g_vhi[(size_t)MROWS * (NKV_*D_)];
__device__ __nv_bfloat16 g_vlo[(size_t)MROWS * (NKV_*D_)];

// ---------------------------------------------------------------------------
// fp32 -> fp16 (row-major). 8 elems/thread.
// ---------------------------------------------------------------------------
__global__ void tofp16_kernel(const float* __restrict__ in,
                              __half* __restrict__ o, int n8)
{
    int idx = blockIdx.x * blockDim.x + threadIdx.x;
    if (idx >= n8) return;
    union { __half b[8]; uint4 u; } uh;
    const float4* in4 = (const float4*)in;
#pragma unroll
    for (int q = 0; q < 2; q++) {
        float4 v = in4[idx * 2 + q];
        uh.b[q * 4 + 0] = __float2half_rn(v.x);
        uh.b[q * 4 + 1] = __float2half_rn(v.y);
        uh.b[q * 4 + 2] = __float2half_rn(v.z);
        uh.b[q * 4 + 3] = __float2half_rn(v.w);
    }
    ((uint4*)o)[idx] = uh.u;
}

// ---------------------------------------------------------------------------
// transpose + fp16: W[K,N] fp32 -> T[N,K] fp16. 32x32 smem tiles.
// ---------------------------------------------------------------------------
__global__ void splitT_kernel(const float* __restrict__ W,
                              __half* __restrict__ T, int K, int N)
{
    __shared__ float s[32][33];
    int tx = threadIdx.x, ty = threadIdx.y;           // (32, 8)
    int n0 = blockIdx.x * 32, k0 = blockIdx.y * 32;
#pragma unroll
    for (int i = 0; i < 4; i++) {
        int k = k0 + ty + i * 8;
        s[ty + i * 8][tx] = W[(size_t)k * N + n0 + tx];
    }
    __syncthreads();
#pragma unroll
    for (int i = 0; i < 4; i++) {
        int n = n0 + ty + i * 8;
        T[(size_t)n * K + k0 + tx] = __float2half_rn(s[tx][ty + i * 8]);
    }
}

// ---------------------------------------------------------------------------
// Plain fp16 GEMM: C = A[M,K] @ B[N,K]^T  (single MMA pass).
// 128x128 CTA tile, BK=32, 8 warps, 2-stage cp.async (proven protocol),
// 2 CTAs/SM (32KB smem).
// ---------------------------------------------------------------------------
#define TILE_BYTES   8192
#define STAGE_BYTES  (2 * TILE_BYTES)        // A | B
#define ST_A 0
#define ST_B 8192
#define GEMM_SMEM_BYTES (2 * STAGE_BYTES)    // 32768 -> 2 CTAs/SM

__global__ __launch_bounds__(256, 2)
void gemm_mma(const __half* __restrict__ A, const __half* __restrict__ B,
              float* __restrict__ C, int M, int N, int K)
{
    extern __shared__ char smem[];
    const uint32_t sbase = smem_to_u32(smem);
    const int tid  = threadIdx.x;
    const int wid  = tid >> 5;
    const int lane = tid & 31;
    const int br = blockIdx.y * 128;
    const int bc = blockIdx.x * 128;
    const int wr = wid & 3;
    const int wc = wid >> 2;

    const int nchunks = K >> 5;

    int r0u = (2 * tid) >> 2, u0 = (2 * tid) & 3;
    int r1u = (2 * tid + 1) >> 2, u1 = (2 * tid + 1) & 3;
    uint32_t so0 = (uint32_t)(r0u * 64 + (u0 ^ ((r0u >> 1) & 3)) * 16);
    uint32_t so1 = (uint32_t)(r1u * 64 + (u1 ^ ((r1u >> 1) & 3)) * 16);

    float acc[2][8][4];
#pragma unroll
    for (int i = 0; i < 2; i++)
#pragma unroll
        for (int j = 0; j < 8; j++)
#pragma unroll
            for (int q = 0; q < 4; q++) acc[i][j][q] = 0.f;

    const int arow0 = wr * 32 + (lane & 15);
    const int arow1 = arow0 + 16;
    const int khalf = lane >> 4;

    auto issue_loads = [&](int c, int stage) {
        uint32_t sb = sbase + stage * STAGE_BYTES;
        const __half* pA = A + (size_t)br * K + c * 32;
        const __half* pB = B + (size_t)bc * K + c * 32;
        size_t g0 = (size_t)r0u * K + u0 * 8;
        size_t g1 = (size_t)r1u * K + u1 * 8;
        cpasync16(sb + ST_A + so0, pA + g0);
        cpasync16(sb + ST_A + so1, pA + g1);
        cpasync16(sb + ST_B + so0, pB + g0);
        cpasync16(sb + ST_B + so1, pB + g1);
    };

    issue_loads(0, 0);
    CP_COMMIT();

    for (int c = 0; c < nchunks; c++) {
        if (c + 1 < nchunks) {
            issue_loads(c + 1, (c + 1) & 1);
            CP_COMMIT();
            CP_WAIT(1);
        } else {
            CP_WAIT(0);
        }
        __syncthreads();

        uint32_t sA = sbase + (c & 1) * STAGE_BYTES;

#pragma unroll
        for (int kk = 0; kk < 2; kk++) {
            uint32_t ah[2][4];
#pragma unroll
            for (int mt = 0; mt < 2; mt++) {
                int row = (mt ? arow1 : arow0);
                int cc  = (kk * 2 + khalf) ^ ((row >> 1) & 3);
                ldsm4(ah[mt], sA + ST_A + (uint32_t)(row * 64 + cc * 16));
            }
#pragma unroll
            for (int ng = 0; ng < 4; ng++) {
                int row = wc * 64 + ng * 16 + (lane & 15);
                int cc  = (kk * 2 + khalf) ^ ((row >> 1) & 3);
                uint32_t bh[4];
                ldsm4(bh, sA + ST_B + (uint32_t)(row * 64 + cc * 16));
#pragma unroll
                for (int hf = 0; hf < 2; hf++) {
                    int j = 2 * ng + hf;
                    mma_fp16(acc[0][j], ah[0], bh[hf], bh[2 + hf]);
                    mma_fp16(acc[1][j], ah[1], bh[hf], bh[2 + hf]);
                }
            }
        }
        __syncthreads();
    }

#pragma unroll
    for (int mt = 0; mt < 2; mt++) {
        int row = br + wr * 32 + mt * 16 + (lane >> 2);
#pragma unroll
        for (int j = 0; j < 8; j++) {
            int col = bc + wc * 64 + j * 8 + (lane & 3) * 2;
            *(float2*)(C + (size_t)row * N + col) =
                make_float2(acc[mt][j][0], acc[mt][j][1]);
            *(float2*)(C + (size_t)(row + 8) * N + col) =
                make_float2(acc[mt][j][2], acc[mt][j][3]);
        }
    }
}

// ---------------------------------------------------------------------------
// RoPE -> bf16 hi/lo. Q variant folds 1/sqrt(D) scale. (unchanged)
// ---------------------------------------------------------------------------
__global__ void rope_bf16_kernel(const float* __restrict__ buf, int nheads, int ld,
                                 const float* __restrict__ cosT,
                                 const float* __restrict__ sinT,
                                 __nv_bfloat16* __restrict__ ohi,
                                 __nv_bfloat16* __restrict__ olo,
                                 float scale, int total)
{
    int idx = blockIdx.x * blockDim.x + threadIdx.x;
    if (idx >= total) return;
    int d2 = idx & 31;
    int h  = (idx >> 5) % nheads;
    int bs = idx / (32 * nheads);
    int s  = bs & (S_ - 1);
    int d  = d2 * 2;
    const float* p = buf + (size_t)bs * ld + h * D_;
    float x1a = p[d],      x1b = p[d + 1];
    float x2a = p[d + 64], x2b = p[d + 65];
    float ca = cosT[s * D_ + d], cb = cosT[s * D_ + d + 1];
    float sa = sinT[s * D_ + d], sb = sinT[s * D_ + d + 1];
    float o1a = (x1a * ca - x2a * sa) * scale;
    float o1b = (x1b * cb - x2b * sb) * scale;
    float o2a = (x2a * ca + x1a * sa) * scale;
    float o2b = (x2b * cb + x1b * sb) * scale;
    uint32_t h1, l1, h2, l2;
    split2pack(o1a, o1b, h1, l1);
    split2pack(o2a, o2b, h2, l2);
    size_t ob = (size_t)bs * (nheads * D_) + h * D_;
    *(uint32_t*)(ohi + ob + d)      = h1;
    *(uint32_t*)(olo + ob + d)      = l1;
    *(uint32_t*)(ohi + ob + d + 64) = h2;
    *(uint32_t*)(olo + ob + d + 64) = l2;
}

// V split: g_qkv cols [2560,3072) -> vhi/vlo [4096][512] (unchanged)
__global__ void vsplit_kernel(const float* __restrict__ qkv,
                              __nv_bfloat16* __restrict__ vhi,
                              __nv_bfloat16* __restrict__ vlo)
{
    int idx = blockIdx.x * blockDim.x + threadIdx.x;   // 4096*64
    int u8 = idx & 63;
    int r  = idx >> 6;
    const float* src = qkv + (size_t)r * NQKV + 2560 + u8 * 8;
    union { __nv_bfloat16 b[8]; uint4 u; } uh, ul;
#pragma unroll
    for (int q = 0; q < 2; q++) {
        float4 v = *(const float4*)(src + q * 4);
        float f[4] = {v.x, v.y, v.z, v.w};
#pragma unroll
        for (int i = 0; i < 4; i++) {
            __nv_bfloat16 hh = __float2bfloat16_rn(f[i]);
            uh.b[q * 4 + i] = hh;
            ul.b[q * 4 + i] = __float2bfloat16_rn(f[i] - __bfloat162float(hh));
        }
    }
    *(uint4*)(vhi + (size_t)r * 512 + u8 * 8) = uh.u;
    *(uint4*)(vlo + (size_t)r * 512 + u8 * 8) = ul.u;
}

// ---------------------------------------------------------------------------
// Tensor-core flash attention, split-bf16 (proven); epilogue emits fp16.
// ---------------------------------------------------------------------------
#define A_SQH 0
#define A_SQL 32768
#define A_SKV 65536
#define A_STAGE 65536
#define ATT_SMEM_BYTES (65536 + 2*65536)   // 196608

__global__ __launch_bounds__(256, 1)
void attn_tc(const __nv_bfloat16* __restrict__ qhi, const __nv_bfloat16* __restrict__ qlo,
             const __nv_bfloat16* __restrict__ khi, const __nv_bfloat16* __restrict__ klo,
             const __nv_bfloat16* __restrict__ vhi, const __nv_bfloat16* __restrict__ vlo,
             __half* __restrict__ O16,
             const int* __restrict__ seqlen)
{
    extern __shared__ char smem[];
    const uint32_t sb = smem_to_u32(smem);
    const int tid  = threadIdx.x;
    const int wid  = tid >> 5;
    const int lane = tid & 31;
    const int bh = blockIdx.x;                 // 0..31
    const int qt = 15 - blockIdx.y;            // heavy tiles first
    const int b   = bh >> 4;
    const int h   = bh & 15;
    const int kvh = h >> 2;
    const int q0  = qt * 128;
    const int len = seqlen[b];

    // ---- load Q tile (hi/lo) ----
    {
        const __nv_bfloat16* qh = qhi + (size_t)(b * S_ + q0) * (NH_*D_) + h * D_;
        const __nv_bfloat16* ql = qlo + (size_t)(b * S_ + q0) * (NH_*D_) + h * D_;
#pragma unroll
        for (int i = 0; i < 8; i++) {
            int g = i * 256 + tid;
            int r = g >> 4, u = g & 15;
            uint32_t so = (uint32_t)(r * 256 + ((u ^ (r & 7)) * 16));
            size_t go = (size_t)r * (NH_*D_) + u * 8;
            cpasync16(sb + A_SQH + so, qh + go);
            cpasync16(sb + A_SQL + so, ql + go);
        }
    }

    const int e  = min(q0 + 128, len);
    const int nt = (e + 63) >> 6;

    auto load_kv = [&](int t, int stage) {
        uint32_t st = sb + A_SKV + stage * A_STAGE;
        size_t base = (size_t)(b * S_ + t * 64) * (NKV_*D_) + kvh * D_;
#pragma unroll
        for (int i = 0; i < 4; i++) {
            int g = i * 256 + tid;
            int r = g >> 4, u = g & 15;
            uint32_t so = (uint32_t)(r * 256 + ((u ^ (r & 7)) * 16));
            size_t go = base + (size_t)r * (NKV_*D_) + u * 8;
            cpasync16(st + so,         khi + go);
            cpasync16(st + 16384 + so, klo + go);
            cpasync16(st + 32768 + so, vhi + go);
            cpasync16(st + 49152 + so, vlo + go);
        }
    };

    load_kv(0, 0);
    CP_COMMIT();

    float out[16][4];
#pragma unroll
    for (int j = 0; j < 16; j++)
#pragma unroll
        for (int q = 0; q < 4; q++) out[j][q] = 0.f;
    float m0 = -1e30f, m1 = -1e30f, l0 = 0.f, l1 = 0.f;

    const int wrow = q0 + wid * 16;

    for (int t = 0; t < nt; t++) {
        if (t + 1 < nt) { load_kv(t + 1, (t + 1) & 1); CP_COMMIT(); CP_WAIT(1); }
        else            { CP_WAIT(0); }
        __syncthreads();

        const int k0 = t * 64;
        if (k0 <= wrow + 15) {
            uint32_t sK = sb + A_SKV + (t & 1) * A_STAGE;
            uint32_t sV = sK + 32768;

            float s[8][4];
#pragma unroll
            for (int j = 0; j < 8; j++)
#pragma unroll
                for (int q = 0; q < 4; q++) s[j][q] = 0.f;

#pragma unroll
            for (int kk = 0; kk < 8; kk++) {
                int ar = wid * 16 + (lane & 15);
                int au = 2 * kk + (lane >> 4);
                uint32_t aso = (uint32_t)(ar * 256 + ((au ^ (ar & 7)) * 16));
                uint32_t ah[4], al[4];
                ldsm4(ah, sb + A_SQH + aso);
                ldsm4(al, sb + A_SQL + aso);
#pragma unroll
                for (int ng = 0; ng < 4; ng++) {
                    int br = ng * 16 + (lane & 15);
                    uint32_t bso = (uint32_t)(br * 256 + ((au ^ (br & 7)) * 16));
                    uint32_t bhf[4], blf[4];
                    ldsm4(bhf, sK + bso);
                    ldsm4(blf, sK + 16384 + bso);
#pragma unroll
                    for (int hf = 0; hf < 2; hf++) {
                        int j = 2 * ng + hf;
                        mma_bf16(s[j], ah, bhf[hf], bhf[2 + hf]);
                        mma_bf16(s[j], ah, blf[hf], blf[2 + hf]);
                        mma_bf16(s[j], al, bhf[hf], bhf[2 + hf]);
                    }
                }
            }

            const int qr0 = wrow + (lane >> 2);
            bool fullvalid = (k0 + 63 <= wrow) && (k0 + 63 < len);
            if (!fullvalid) {
#pragma unroll
                for (int j = 0; j < 8; j++) {
                    int kgb = k0 + j * 8 + (lane & 3) * 2;
#pragma unroll
                    for (int q = 0; q < 4; q++) {
                        int kg = kgb + (q & 1);
                        int qg = qr0 + ((q >> 1) << 3);
                        if (kg > qg || kg >= len) s[j][q] = -1e30f;
                    }
                }
            }

            float mx0 = -1e30f, mx1 = -1e30f;
#pragma unroll
            for (int j = 0; j < 8; j++) {
                mx0 = fmaxf(mx0, fmaxf(s[j][0], s[j][1]));
                mx1 = fmaxf(mx1, fmaxf(s[j][2], s[j][3]));
            }
#pragma unroll
            for (int off = 1; off <= 2; off <<= 1) {
                mx0 = fmaxf(mx0, __shfl_xor_sync(0xffffffffu, mx0, off));
                mx1 = fmaxf(mx1, __shfl_xor_sync(0xffffffffu, mx1, off));
            }
            float nm0 = fmaxf(m0, mx0), nm1 = fmaxf(m1, mx1);
            float sc0 = __expf(m0 - nm0), sc1 = __expf(m1 - nm1);
            m0 = nm0; m1 = nm1;
            float sum0 = 0.f, sum1 = 0.f;
#pragma unroll
            for (int j = 0; j < 8; j++) {
                s[j][0] = __expf(s[j][0] - nm0);
                s[j][1] = __expf(s[j][1] - nm0);
                s[j][2] = __expf(s[j][2] - nm1);
                s[j][3] = __expf(s[j][3] - nm1);
                sum0 += s[j][0] + s[j][1];
                sum1 += s[j][2] + s[j][3];
            }
#pragma unroll
            for (int off = 1; off <= 2; off <<= 1) {
                sum0 += __shfl_xor_sync(0xffffffffu, sum0, off);
                sum1 += __shfl_xor_sync(0xffffffffu, sum1, off);
            }
            l0 = l0 * sc0 + sum0;
            l1 = l1 * sc1 + sum1;
#pragma unroll
            for (int j = 0; j < 16; j++) {
                out[j][0] *= sc0; out[j][1] *= sc0;
                out[j][2] *= sc1; out[j][3] *= sc1;
            }

#pragma unroll
            for (int jk = 0; jk < 4; jk++) {
                uint32_t ph[4], pl[4];
                split2pack(s[2*jk][0],   s[2*jk][1],   ph[0], pl[0]);
                split2pack(s[2*jk][2],   s[2*jk][3],   ph[1], pl[1]);
                split2pack(s[2*jk+1][0], s[2*jk+1][1], ph[2], pl[2]);
                split2pack(s[2*jk+1][2], s[2*jk+1][3], ph[3], pl[3]);
#pragma unroll
                for (int gn = 0; gn < 8; gn++) {
                    int vr = jk * 16 + (lane & 15);
                    int vu = 2 * gn + (lane >> 4);
                    uint32_t vso = (uint32_t)(vr * 256 + ((vu ^ (vr & 7)) * 16));
                    uint32_t vh4[4], vl4[4];
                    ldsm4t(vh4, sV + vso);
                    ldsm4t(vl4, sV + 16384 + vso);
#pragma unroll
                    for (int hf = 0; hf < 2; hf++) {
                        int jn = 2 * gn + hf;
                        mma_bf16(out[jn], ph, vh4[2*hf], vh4[2*hf + 1]);
                        mma_bf16(out[jn], pl, vh4[2*hf], vh4[2*hf + 1]);
                        mma_bf16(out[jn], ph, vl4[2*hf], vl4[2*hf + 1]);
                    }
                }
            }
        }
        __syncthreads();
    }

    // ---- epilogue: normalize, store fp16 ----
    float i0 = 1.0f / l0, i1 = 1.0f / l1;
    size_t ro0 = (size_t)(b * S_ + wrow + (lane >> 2)) * (NH_*D_) + h * D_;
    size_t ro1 = ro0 + (size_t)8 * (NH_*D_);
#pragma unroll
    for (int jn = 0; jn < 16; jn++) {
        int col = jn * 8 + (lane & 3) * 2;
        *(uint32_t*)(O16 + ro0 + col) = pack2h(out[jn][0] * i0, out[jn][1] * i0);
        *(uint32_t*)(O16 + ro1 + col) = pack2h(out[jn][2] * i1, out[jn][3] * i1);
    }
}

// ---------------------------------------------------------------------------
// Launch
// ---------------------------------------------------------------------------
extern "C" void kernel_launch(void* const* d_in, const int* in_sizes, int n_in,
                              void* d_out, int out_size)
{
    const float* x    = (const float*)d_in[0];
    const int*   seq  = (const int*)  d_in[1];
    const float* fcos = (const float*)d_in[2];
    const float* fsin = (const float*)d_in[3];
    const float* Wq   = (const float*)d_in[4];
    const float* Wkv  = (const float*)d_in[5];
    const float* Wo   = (const float*)d_in[6];
    float* out = (float*)d_out;

    float *qkv;
    cudaGetSymbolAddress((void**)&qkv, g_qkv);
    __half *x16, *a16, *wh, *woh;
    __nv_bfloat16 *qhi, *qlo, *khi, *klo, *vhi, *vlo;
    cudaGetSymbolAddress((void**)&x16, g_x16);
    cudaGetSymbolAddress((void**)&a16, g_a16);
    cudaGetSymbolAddress((void**)&wh,  g_wh);
    cudaGetSymbolAddress((void**)&woh, g_woh);
    cudaGetSymbolAddress((void**)&qhi, g_qhi);
    cudaGetSymbolAddress((void**)&qlo, g_qlo);
    cudaGetSymbolAddress((void**)&khi, g_khi);
    cudaGetSymbolAddress((void**)&klo, g_klo);
    cudaGetSymbolAddress((void**)&vhi, g_vhi);
    cudaGetSymbolAddress((void**)&vlo, g_vlo);

    cudaFuncSetAttribute(gemm_mma, cudaFuncAttributeMaxDynamicSharedMemorySize, GEMM_SMEM_BYTES);
    cudaFuncSetAttribute(attn_tc,  cudaFuncAttributeMaxDynamicSharedMemorySize, ATT_SMEM_BYTES);

    dim3 blk(256);

    // 0) preprocessing: x -> fp16; W -> fp16 transposed
    {
        int n8 = MROWS * H_ / 8;
        tofp16_kernel<<<(n8 + 255) / 256, 256>>>(x, x16, n8);
        dim3 tb(32, 8);
        splitT_kernel<<<dim3((NH_*D_)/32,    H_/32), tb>>>(Wq,  wh,                     H_, NH_*D_);
        splitT_kernel<<<dim3((2*NKV_*D_)/32, H_/32), tb>>>(Wkv, wh + (size_t)2048 * H_, H_, 2*NKV_*D_);
        splitT_kernel<<<dim3(H_/32,          H_/32), tb>>>(Wo,  woh, H_, H_);
    }

    // 1) fused QKV projection (plain fp16, single pass)
    gemm_mma<<<dim3(24, 32), blk, GEMM_SMEM_BYTES>>>(x16, wh, qkv, MROWS, NQKV, H_);

    // 2) RoPE -> bf16 hi/lo (Q folds softmax scale); V split
    {
        int tq = MROWS * NH_ * 32;
        int tk = MROWS * NKV_ * 32;
        rope_bf16_kernel<<<(tq + 255) / 256, 256>>>(qkv,        NH_,  NQKV, fcos, fsin, qhi, qlo, QSCALE, tq);
        rope_bf16_kernel<<<(tk + 255) / 256, 256>>>(qkv + 2048, NKV_, NQKV, fcos, fsin, khi, klo, 1.0f,   tk);
        int tv = MROWS * 64;
        vsplit_kernel<<<(tv + 255) / 256, 256>>>(qkv, vhi, vlo);
    }

    // 3) attention (tensor-core, split-bf16, emits fp16)
    attn_tc<<<dim3(32, 16), blk, ATT_SMEM_BYTES>>>(qhi, qlo, khi, klo, vhi, vlo, a16, seq);

    // 4) output projection (plain fp16, single pass)
    gemm_mma<<<dim3(16, 32), blk, GEMM_SMEM_BYTES>>>(a16, woh, out, MROWS, H_, H_);
}

// round 13
// speedup vs baseline: 2.4761x; 1.0847x over previous
#include <cuda_runtime.h>
#include <cuda_bf16.h>
#include <cuda_fp16.h>
#include <cstdint>
#include <cstddef>

// Problem constants
#define B_   2
#define S_   2048
#define H_   2048
#define NH_  16
#define NKV_ 4
#define D_   128
#define MROWS (B_*S_)          // 4096
#define NQKV 3072              // 2048 q | 512 k | 512 v
#define QSCALE 0.08838834764831845f

// ---------------------------------------------------------------------------
// PTX helpers (sm_100-safe: mma.sync / ldmatrix / cp.async only)
// ---------------------------------------------------------------------------
__device__ __forceinline__ uint32_t smem_to_u32(const void* p) {
    uint32_t a;
    asm("{ .reg .u64 t; cvta.to.shared.u64 t, %1; cvt.u32.u64 %0, t; }" : "=r"(a) : "l"(p));
    return a;
}
__device__ __forceinline__ void ldsm4(uint32_t* r, uint32_t addr) {
    asm volatile("ldmatrix.sync.aligned.m8n8.x4.shared.b16 {%0,%1,%2,%3}, [%4];"
        : "=r"(r[0]), "=r"(r[1]), "=r"(r[2]), "=r"(r[3]) : "r"(addr));
}
__device__ __forceinline__ void ldsm4t(uint32_t* r, uint32_t addr) {
    asm volatile("ldmatrix.sync.aligned.m8n8.x4.trans.shared.b16 {%0,%1,%2,%3}, [%4];"
        : "=r"(r[0]), "=r"(r[1]), "=r"(r[2]), "=r"(r[3]) : "r"(addr));
}
__device__ __forceinline__ void mma_fp16(float* d, const uint32_t* a, uint32_t b0, uint32_t b1) {
    asm volatile("mma.sync.aligned.m16n8k16.row.col.f32.f16.f16.f32 "
        "{%0,%1,%2,%3}, {%4,%5,%6,%7}, {%8,%9}, {%0,%1,%2,%3};"
        : "+f"(d[0]), "+f"(d[1]), "+f"(d[2]), "+f"(d[3])
        : "r"(a[0]), "r"(a[1]), "r"(a[2]), "r"(a[3]), "r"(b0), "r"(b1));
}
__device__ __forceinline__ void cpasync16(uint32_t saddr, const void* g) {
    asm volatile("cp.async.cg.shared.global [%0], [%1], 16;" :: "r"(saddr), "l"(g));
}
#define CP_COMMIT() asm volatile("cp.async.commit_group;" ::: "memory")
#define CP_WAIT(n)  asm volatile("cp.async.wait_group %0;" :: "n"(n) : "memory")

__device__ __forceinline__ void split2pack_h(float a, float b, uint32_t& hi, uint32_t& lo) {
    __half ah = __float2half_rn(a);
    __half bh = __float2half_rn(b);
    __half al = __float2half_rn(a - __half2float(ah));
    __half bl = __float2half_rn(b - __half2float(bh));
    hi = (uint32_t)(*(uint16_t*)&ah) | ((uint32_t)(*(uint16_t*)&bh) << 16);
    lo = (uint32_t)(*(uint16_t*)&al) | ((uint32_t)(*(uint16_t*)&bl) << 16);
}
__device__ __forceinline__ uint32_t pack2h(float a, float b) {
    __half ah = __float2half_rn(a);
    __half bh = __float2half_rn(b);
    return (uint32_t)(*(uint16_t*)&ah) | ((uint32_t)(*(uint16_t*)&bh) << 16);
}

// ---------------------------------------------------------------------------
// Scratch (device globals)
// ---------------------------------------------------------------------------
__device__ float g_qkv[(size_t)MROWS * NQKV];        // fp32 q|k|v projections

__device__ __half g_x16[(size_t)MROWS * H_];         // fp16 x
__device__ __half g_a16[(size_t)MROWS * H_];         // fp16 attention out
__device__ __half g_wh [(size_t)NQKV * H_];          // fp16 Wq|Wkv transposed [3072,2048]
__device__ __half g_woh[(size_t)H_ * H_];            // fp16 Wo transposed
// attention operands (fp16)
__device__ __half g_qhi[(size_t)MROWS * (NH_*D_)];
__device__ __half g_qlo[(size_t)MROWS * (NH_*D_)];
__device__ __half g_k16[(size_t)MROWS * (NKV_*D_)];
__device__ __half g_vhi[(size_t)MROWS * (NKV_*D_)];
__device__ __half g_vlo[(size_t)MROWS * (NKV_*D_)];

// ---------------------------------------------------------------------------
// fp32 -> fp16 (row-major). 8 elems/thread.
// ---------------------------------------------------------------------------
__global__ void tofp16_kernel(const float* __restrict__ in,
                              __half* __restrict__ o, int n8)
{
    int idx = blockIdx.x * blockDim.x + threadIdx.x;
    if (idx >= n8) return;
    union { __half b[8]; uint4 u; } uh;
    const float4* in4 = (const float4*)in;
#pragma unroll
    for (int q = 0; q < 2; q++) {
        float4 v = in4[idx * 2 + q];
        uh.b[q * 4 + 0] = __float2half_rn(v.x);
        uh.b[q * 4 + 1] = __float2half_rn(v.y);
        uh.b[q * 4 + 2] = __float2half_rn(v.z);
        uh.b[q * 4 + 3] = __float2half_rn(v.w);
    }
    ((uint4*)o)[idx] = uh.u;
}

// ---------------------------------------------------------------------------
// transpose + fp16: W[K,N] fp32 -> T[N,K] fp16. 32x32 smem tiles.
// ---------------------------------------------------------------------------
__global__ void splitT_kernel(const float* __restrict__ W,
                              __half* __restrict__ T, int K, int N)
{
    __shared__ float s[32][33];
    int tx = threadIdx.x, ty = threadIdx.y;           // (32, 8)
    int n0 = blockIdx.x * 32, k0 = blockIdx.y * 32;
#pragma unroll
    for (int i = 0; i < 4; i++) {
        int k = k0 + ty + i * 8;
        s[ty + i * 8][tx] = W[(size_t)k * N + n0 + tx];
    }
    __syncthreads();
#pragma unroll
    for (int i = 0; i < 4; i++) {
        int n = n0 + ty + i * 8;
        T[(size_t)n * K + k0 + tx] = __float2half_rn(s[tx][ty + i * 8]);
    }
}

// ---------------------------------------------------------------------------
// Plain fp16 GEMM (R12-proven): C = A[M,K] @ B[N,K]^T, single MMA pass.
// ---------------------------------------------------------------------------
#define TILE_BYTES   8192
#define STAGE_BYTES  (2 * TILE_BYTES)        // A | B
#define ST_A 0
#define ST_B 8192
#define GEMM_SMEM_BYTES (2 * STAGE_BYTES)    // 32768 -> 2 CTAs/SM

__global__ __launch_bounds__(256, 2)
void gemm_mma(const __half* __restrict__ A, const __half* __restrict__ B,
              float* __restrict__ C, int M, int N, int K)
{
    extern __shared__ char smem[];
    const uint32_t sbase = smem_to_u32(smem);
    const int tid  = threadIdx.x;
    const int wid  = tid >> 5;
    const int lane = tid & 31;
    const int br = blockIdx.y * 128;
    const int bc = blockIdx.x * 128;
    const int wr = wid & 3;
    const int wc = wid >> 2;

    const int nchunks = K >> 5;

    int r0u = (2 * tid) >> 2, u0 = (2 * tid) & 3;
    int r1u = (2 * tid + 1) >> 2, u1 = (2 * tid + 1) & 3;
    uint32_t so0 = (uint32_t)(r0u * 64 + (u0 ^ ((r0u >> 1) & 3)) * 16);
    uint32_t so1 = (uint32_t)(r1u * 64 + (u1 ^ ((r1u >> 1) & 3)) * 16);

    float acc[2][8][4];
#pragma unroll
    for (int i = 0; i < 2; i++)
#pragma unroll
        for (int j = 0; j < 8; j++)
#pragma unroll
            for (int q = 0; q < 4; q++) acc[i][j][q] = 0.f;

    const int arow0 = wr * 32 + (lane & 15);
    const int arow1 = arow0 + 16;
    const int khalf = lane >> 4;

    auto issue_loads = [&](int c, int stage) {
        uint32_t sb = sbase + stage * STAGE_BYTES;
        const __half* pA = A + (size_t)br * K + c * 32;
        const __half* pB = B + (size_t)bc * K + c * 32;
        size_t g0 = (size_t)r0u * K + u0 * 8;
        size_t g1 = (size_t)r1u * K + u1 * 8;
        cpasync16(sb + ST_A + so0, pA + g0);
        cpasync16(sb + ST_A + so1, pA + g1);
        cpasync16(sb + ST_B + so0, pB + g0);
        cpasync16(sb + ST_B + so1, pB + g1);
    };

    issue_loads(0, 0);
    CP_COMMIT();

    for (int c = 0; c < nchunks; c++) {
        if (c + 1 < nchunks) {
            issue_loads(c + 1, (c + 1) & 1);
            CP_COMMIT();
            CP_WAIT(1);
        } else {
            CP_WAIT(0);
        }
        __syncthreads();

        uint32_t sA = sbase + (c & 1) * STAGE_BYTES;

#pragma unroll
        for (int kk = 0; kk < 2; kk++) {
            uint32_t ah[2][4];
#pragma unroll
            for (int mt = 0; mt < 2; mt++) {
                int row = (mt ? arow1 : arow0);
                int cc  = (kk * 2 + khalf) ^ ((row >> 1) & 3);
                ldsm4(ah[mt], sA + ST_A + (uint32_t)(row * 64 + cc * 16));
            }
#pragma unroll
            for (int ng = 0; ng < 4; ng++) {
                int row = wc * 64 + ng * 16 + (lane & 15);
                int cc  = (kk * 2 + khalf) ^ ((row >> 1) & 3);
                uint32_t bh[4];
                ldsm4(bh, sA + ST_B + (uint32_t)(row * 64 + cc * 16));
#pragma unroll
                for (int hf = 0; hf < 2; hf++) {
                    int j = 2 * ng + hf;
                    mma_fp16(acc[0][j], ah[0], bh[hf], bh[2 + hf]);
                    mma_fp16(acc[1][j], ah[1], bh[hf], bh[2 + hf]);
                }
            }
        }
        __syncthreads();
    }

#pragma unroll
    for (int mt = 0; mt < 2; mt++) {
        int row = br + wr * 32 + mt * 16 + (lane >> 2);
#pragma unroll
        for (int j = 0; j < 8; j++) {
            int col = bc + wc * 64 + j * 8 + (lane & 3) * 2;
            *(float2*)(C + (size_t)row * N + col) =
                make_float2(acc[mt][j][0], acc[mt][j][1]);
            *(float2*)(C + (size_t)(row + 8) * N + col) =
                make_float2(acc[mt][j][2], acc[mt][j][3]);
        }
    }
}

// ---------------------------------------------------------------------------
// RoPE -> fp16. If split: writes hi + residual lo; else single plane.
// ---------------------------------------------------------------------------
__global__ void rope_fp16_kernel(const float* __restrict__ buf, int nheads, int ld,
                                 const float* __restrict__ cosT,
                                 const float* __restrict__ sinT,
                                 __half* __restrict__ ohi,
                                 __half* __restrict__ olo,   // may be null -> single plane
                                 float scale, int total)
{
    int idx = blockIdx.x * blockDim.x + threadIdx.x;
    if (idx >= total) return;
    int d2 = idx & 31;
    int h  = (idx >> 5) % nheads;
    int bs = idx / (32 * nheads);
    int s  = bs & (S_ - 1);
    int d  = d2 * 2;
    const float* p = buf + (size_t)bs * ld + h * D_;
    float x1a = p[d],      x1b = p[d + 1];
    float x2a = p[d + 64], x2b = p[d + 65];
    float ca = cosT[s * D_ + d], cb = cosT[s * D_ + d + 1];
    float sa = sinT[s * D_ + d], sb = sinT[s * D_ + d + 1];
    float o1a = (x1a * ca - x2a * sa) * scale;
    float o1b = (x1b * cb - x2b * sb) * scale;
    float o2a = (x2a * ca + x1a * sa) * scale;
    float o2b = (x2b * cb + x1b * sb) * scale;
    size_t ob = (size_t)bs * (nheads * D_) + h * D_;
    if (olo) {
        uint32_t h1, l1, h2, l2;
        split2pack_h(o1a, o1b, h1, l1);
        split2pack_h(o2a, o2b, h2, l2);
        *(uint32_t*)(ohi + ob + d)      = h1;
        *(uint32_t*)(olo + ob + d)      = l1;
        *(uint32_t*)(ohi + ob + d + 64) = h2;
        *(uint32_t*)(olo + ob + d + 64) = l2;
    } else {
        *(uint32_t*)(ohi + ob + d)      = pack2h(o1a, o1b);
        *(uint32_t*)(ohi + ob + d + 64) = pack2h(o2a, o2b);
    }
}

// V split: g_qkv cols [2560,3072) -> vhi/vlo fp16 [4096][512]
__global__ void vsplit_kernel(const float* __restrict__ qkv,
                              __half* __restrict__ vhi,
                              __half* __restrict__ vlo)
{
    int idx = blockIdx.x * blockDim.x + threadIdx.x;   // 4096*64
    int u8 = idx & 63;
    int r  = idx >> 6;
    const float* src = qkv + (size_t)r * NQKV + 2560 + u8 * 8;
    union { __half b[8]; uint4 u; } uh, ul;
#pragma unroll
    for (int q = 0; q < 2; q++) {
        float4 v = *(const float4*)(src + q * 4);
        float f[4] = {v.x, v.y, v.z, v.w};
#pragma unroll
        for (int i = 0; i < 4; i++) {
            __half hh = __float2half_rn(f[i]);
            uh.b[q * 4 + i] = hh;
            ul.b[q * 4 + i] = __float2half_rn(f[i] - __half2float(hh));
        }
    }
    *(uint4*)(vhi + (size_t)r * 512 + u8 * 8) = uh.u;
    *(uint4*)(vlo + (size_t)r * 512 + u8 * 8) = ul.u;
}

// ---------------------------------------------------------------------------
// Tensor-core flash attention, fp16 2-pass:
//   scores = (Qhi + Qlo) K^T      (K single plane)
//   out    = P (Vhi + Vlo)        (P single plane)
// smem: Qhi|Qlo persistent (64KB) + 2 stages x (K|Vhi|Vlo) (48KB each).
// ---------------------------------------------------------------------------
#define A_SQH 0
#define A_SQL 32768
#define A_SKV 65536
#define A_STAGE 49152
#define ATT_SMEM_BYTES (65536 + 2*49152)   // 163840

__global__ __launch_bounds__(256, 1)
void attn_tc(const __half* __restrict__ qhi, const __half* __restrict__ qlo,
             const __half* __restrict__ k16,
             const __half* __restrict__ vhi, const __half* __restrict__ vlo,
             __half* __restrict__ O16,
             const int* __restrict__ seqlen)
{
    extern __shared__ char smem[];
    const uint32_t sb = smem_to_u32(smem);
    const int tid  = threadIdx.x;
    const int wid  = tid >> 5;
    const int lane = tid & 31;
    const int bh = blockIdx.x;                 // 0..31
    const int qt = 15 - blockIdx.y;            // heavy tiles first
    const int b   = bh >> 4;
    const int h   = bh & 15;
    const int kvh = h >> 2;
    const int q0  = qt * 128;
    const int len = seqlen[b];

    // ---- load Q tile (hi/lo), 128 rows x 16 units each ----
    {
        const __half* qh = qhi + (size_t)(b * S_ + q0) * (NH_*D_) + h * D_;
        const __half* ql = qlo + (size_t)(b * S_ + q0) * (NH_*D_) + h * D_;
#pragma unroll
        for (int i = 0; i < 8; i++) {
            int g = i * 256 + tid;
            int r = g >> 4, u = g & 15;
            uint32_t so = (uint32_t)(r * 256 + ((u ^ (r & 7)) * 16));
            size_t go = (size_t)r * (NH_*D_) + u * 8;
            cpasync16(sb + A_SQH + so, qh + go);
            cpasync16(sb + A_SQL + so, ql + go);
        }
    }

    const int e  = min(q0 + 128, len);
    const int nt = (e + 63) >> 6;

    auto load_kv = [&](int t, int stage) {
        uint32_t st = sb + A_SKV + stage * A_STAGE;
        size_t base = (size_t)(b * S_ + t * 64) * (NKV_*D_) + kvh * D_;
#pragma unroll
        for (int i = 0; i < 4; i++) {
            int g = i * 256 + tid;
            int r = g >> 4, u = g & 15;
            uint32_t so = (uint32_t)(r * 256 + ((u ^ (r & 7)) * 16));
            size_t go = base + (size_t)r * (NKV_*D_) + u * 8;
            cpasync16(st + so,         k16 + go);
            cpasync16(st + 16384 + so, vhi + go);
            cpasync16(st + 32768 + so, vlo + go);
        }
    };

    load_kv(0, 0);
    CP_COMMIT();

    float out[16][4];
#pragma unroll
    for (int j = 0; j < 16; j++)
#pragma unroll
        for (int q = 0; q < 4; q++) out[j][q] = 0.f;
    float m0 = -1e30f, m1 = -1e30f, l0 = 0.f, l1 = 0.f;

    const int wrow = q0 + wid * 16;            // warp's first q row (global)

    for (int t = 0; t < nt; t++) {
        if (t + 1 < nt) { load_kv(t + 1, (t + 1) & 1); CP_COMMIT(); CP_WAIT(1); }
        else            { CP_WAIT(0); }
        __syncthreads();

        const int k0 = t * 64;
        if (k0 <= wrow + 15) {                 // warp has at least one unmasked row
            uint32_t sK = sb + A_SKV + (t & 1) * A_STAGE;
            uint32_t sV = sK + 16384;

            // ---- scores S = (Qhi+Qlo) K^T (m16 x 64), 2 passes ----
            float s[8][4];
#pragma unroll
            for (int j = 0; j < 8; j++)
#pragma unroll
                for (int q = 0; q < 4; q++) s[j][q] = 0.f;

#pragma unroll
            for (int kk = 0; kk < 8; kk++) {
                int ar = wid * 16 + (lane & 15);
                int au = 2 * kk + (lane >> 4);
                uint32_t aso = (uint32_t)(ar * 256 + ((au ^ (ar & 7)) * 16));
                uint32_t ah[4], al[4];
                ldsm4(ah, sb + A_SQH + aso);
                ldsm4(al, sb + A_SQL + aso);
#pragma unroll
                for (int ng = 0; ng < 4; ng++) {
                    int br = ng * 16 + (lane & 15);
                    uint32_t bso = (uint32_t)(br * 256 + ((au ^ (br & 7)) * 16));
                    uint32_t bk[4];
                    ldsm4(bk, sK + bso);
#pragma unroll
                    for (int hf = 0; hf < 2; hf++) {
                        int j = 2 * ng + hf;
                        mma_fp16(s[j], ah, bk[hf], bk[2 + hf]);
                        mma_fp16(s[j], al, bk[hf], bk[2 + hf]);
                    }
                }
            }

            // ---- mask ----
            const int qr0 = wrow + (lane >> 2);
            bool fullvalid = (k0 + 63 <= wrow) && (k0 + 63 < len);
            if (!fullvalid) {
#pragma unroll
                for (int j = 0; j < 8; j++) {
                    int kgb = k0 + j * 8 + (lane & 3) * 2;
#pragma unroll
                    for (int q = 0; q < 4; q++) {
                        int kg = kgb + (q & 1);
                        int qg = qr0 + ((q >> 1) << 3);
                        if (kg > qg || kg >= len) s[j][q] = -1e30f;
                    }
                }
            }

            // ---- online softmax ----
            float mx0 = -1e30f, mx1 = -1e30f;
#pragma unroll
            for (int j = 0; j < 8; j++) {
                mx0 = fmaxf(mx0, fmaxf(s[j][0], s[j][1]));
                mx1 = fmaxf(mx1, fmaxf(s[j][2], s[j][3]));
            }
#pragma unroll
            for (int off = 1; off <= 2; off <<= 1) {
                mx0 = fmaxf(mx0, __shfl_xor_sync(0xffffffffu, mx0, off));
                mx1 = fmaxf(mx1, __shfl_xor_sync(0xffffffffu, mx1, off));
            }
            float nm0 = fmaxf(m0, mx0), nm1 = fmaxf(m1, mx1);
            float sc0 = __expf(m0 - nm0), sc1 = __expf(m1 - nm1);
            m0 = nm0; m1 = nm1;
            float sum0 = 0.f, sum1 = 0.f;
#pragma unroll
            for (int j = 0; j < 8; j++) {
                s[j][0] = __expf(s[j][0] - nm0);
                s[j][1] = __expf(s[j][1] - nm0);
                s[j][2] = __expf(s[j][2] - nm1);
                s[j][3] = __expf(s[j][3] - nm1);
                sum0 += s[j][0] + s[j][1];
                sum1 += s[j][2] + s[j][3];
            }
#pragma unroll
            for (int off = 1; off <= 2; off <<= 1) {
                sum0 += __shfl_xor_sync(0xffffffffu, sum0, off);
                sum1 += __shfl_xor_sync(0xffffffffu, sum1, off);
            }
            l0 = l0 * sc0 + sum0;
            l1 = l1 * sc1 + sum1;
#pragma unroll
            for (int j = 0; j < 16; j++) {
                out[j][0] *= sc0; out[j][1] *= sc0;
                out[j][2] *= sc1; out[j][3] *= sc1;
            }

            // ---- PV: out += P (Vhi + Vlo), P single plane, 2 passes ----
#pragma unroll
            for (int jk = 0; jk < 4; jk++) {
                uint32_t pf[4];
                pf[0] = pack2h(s[2*jk][0],   s[2*jk][1]);
                pf[1] = pack2h(s[2*jk][2],   s[2*jk][3]);
                pf[2] = pack2h(s[2*jk+1][0], s[2*jk+1][1]);
                pf[3] = pack2h(s[2*jk+1][2], s[2*jk+1][3]);
#pragma unroll
                for (int gn = 0; gn < 8; gn++) {
                    int vr = jk * 16 + (lane & 15);
                    int vu = 2 * gn + (lane >> 4);
                    uint32_t vso = (uint32_t)(vr * 256 + ((vu ^ (vr & 7)) * 16));
                    uint32_t vh4[4], vl4[4];
                    ldsm4t(vh4, sV + vso);
                    ldsm4t(vl4, sV + 16384 + vso);
#pragma unroll
                    for (int hf = 0; hf < 2; hf++) {
                        int jn = 2 * gn + hf;
                        mma_fp16(out[jn], pf, vh4[2*hf], vh4[2*hf + 1]);
                        mma_fp16(out[jn], pf, vl4[2*hf], vl4[2*hf + 1]);
                    }
                }
            }
        }
        __syncthreads();
    }

    // ---- epilogue: normalize, store fp16 ----
    float i0 = 1.0f / l0, i1 = 1.0f / l1;
    size_t ro0 = (size_t)(b * S_ + wrow + (lane >> 2)) * (NH_*D_) + h * D_;
    size_t ro1 = ro0 + (size_t)8 * (NH_*D_);
#pragma unroll
    for (int jn = 0; jn < 16; jn++) {
        int col = jn * 8 + (lane & 3) * 2;
        *(uint32_t*)(O16 + ro0 + col) = pack2h(out[jn][0] * i0, out[jn][1] * i0);
        *(uint32_t*)(O16 + ro1 + col) = pack2h(out[jn][2] * i1, out[jn][3] * i1);
    }
}

// ---------------------------------------------------------------------------
// Launch
// ---------------------------------------------------------------------------
extern "C" void kernel_launch(void* const* d_in, const int* in_sizes, int n_in,
                              void* d_out, int out_size)
{
    const float* x    = (const float*)d_in[0];
    const int*   seq  = (const int*)  d_in[1];
    const float* fcos = (const float*)d_in[2];
    const float* fsin = (const float*)d_in[3];
    const float* Wq   = (const float*)d_in[4];
    const float* Wkv  = (const float*)d_in[5];
    const float* Wo   = (const float*)d_in[6];
    float* out = (float*)d_out;

    float *qkv;
    cudaGetSymbolAddress((void**)&qkv, g_qkv);
    __half *x16, *a16, *wh, *woh;
    __half *qhi, *qlo, *k16, *vhi, *vlo;
    cudaGetSymbolAddress((void**)&x16, g_x16);
    cudaGetSymbolAddress((void**)&a16, g_a16);
    cudaGetSymbolAddress((void**)&wh,  g_wh);
    cudaGetSymbolAddress((void**)&woh, g_woh);
    cudaGetSymbolAddress((void**)&qhi, g_qhi);
    cudaGetSymbolAddress((void**)&qlo, g_qlo);
    cudaGetSymbolAddress((void**)&k16, g_k16);
    cudaGetSymbolAddress((void**)&vhi, g_vhi);
    cudaGetSymbolAddress((void**)&vlo, g_vlo);

    cudaFuncSetAttribute(gemm_mma, cudaFuncAttributeMaxDynamicSharedMemorySize, GEMM_SMEM_BYTES);
    cudaFuncSetAttribute(attn_tc,  cudaFuncAttributeMaxDynamicSharedMemorySize, ATT_SMEM_BYTES);

    dim3 blk(256);

    // 0) preprocessing: x -> fp16; W -> fp16 transposed
    {
        int n8 = MROWS * H_ / 8;
        tofp16_kernel<<<(n8 + 255) / 256, 256>>>(x, x16, n8);
        dim3 tb(32, 8);
        splitT_kernel<<<dim3((NH_*D_)/32,    H_/32), tb>>>(Wq,  wh,                     H_, NH_*D_);
        splitT_kernel<<<dim3((2*NKV_*D_)/32, H_/32), tb>>>(Wkv, wh + (size_t)2048 * H_, H_, 2*NKV_*D_);
        splitT_kernel<<<dim3(H_/32,          H_/32), tb>>>(Wo,  woh, H_, H_);
    }

    // 1) fused QKV projection (plain fp16, single pass)
    gemm_mma<<<dim3(24, 32), blk, GEMM_SMEM_BYTES>>>(x16, wh, qkv, MROWS, NQKV, H_);

    // 2) RoPE -> fp16 (Q split hi/lo + folded scale; K single plane); V split
    {
        int tq = MROWS * NH_ * 32;
        int tk = MROWS * NKV_ * 32;
        rope_fp16_kernel<<<(tq + 255) / 256, 256>>>(qkv,        NH_,  NQKV, fcos, fsin, qhi, qlo,          QSCALE, tq);
        rope_fp16_kernel<<<(tk + 255) / 256, 256>>>(qkv + 2048, NKV_, NQKV, fcos, fsin, k16, (__half*)0,   1.0f,   tk);
        int tv = MROWS * 64;
        vsplit_kernel<<<(tv + 255) / 256, 256>>>(qkv, vhi, vlo);
    }

    // 3) attention (tensor-core, fp16 2-pass, emits fp16)
    attn_tc<<<dim3(32, 16), blk, ATT_SMEM_BYTES>>>(qhi, qlo, k16, vhi, vlo, a16, seq);

    // 4) output projection (plain fp16, single pass)
    gemm_mma<<<dim3(16, 32), blk, GEMM_SMEM_BYTES>>>(a16, woh, out, MROWS, H_, H_);
}

// round 14
// speedup vs baseline: 2.7336x; 1.1040x over previous
#include <cuda_runtime.h>
#include <cuda_bf16.h>
#include <cuda_fp16.h>
#include <cstdint>
#include <cstddef>

// Problem constants
#define B_   2
#define S_   2048
#define H_   2048
#define NH_  16
#define NKV_ 4
#define D_   128
#define MROWS (B_*S_)          // 4096
#define NQKV 3072              // 2048 q | 512 k | 512 v
#define QSCALE 0.08838834764831845f

// ---------------------------------------------------------------------------
// PTX helpers (sm_100-safe: mma.sync / ldmatrix / cp.async only)
// ---------------------------------------------------------------------------
__device__ __forceinline__ uint32_t smem_to_u32(const void* p) {
    uint32_t a;
    asm("{ .reg .u64 t; cvta.to.shared.u64 t, %1; cvt.u32.u64 %0, t; }" : "=r"(a) : "l"(p));
    return a;
}
__device__ __forceinline__ void ldsm4(uint32_t* r, uint32_t addr) {
    asm volatile("ldmatrix.sync.aligned.m8n8.x4.shared.b16 {%0,%1,%2,%3}, [%4];"
        : "=r"(r[0]), "=r"(r[1]), "=r"(r[2]), "=r"(r[3]) : "r"(addr));
}
__device__ __forceinline__ void ldsm4t(uint32_t* r, uint32_t addr) {
    asm volatile("ldmatrix.sync.aligned.m8n8.x4.trans.shared.b16 {%0,%1,%2,%3}, [%4];"
        : "=r"(r[0]), "=r"(r[1]), "=r"(r[2]), "=r"(r[3]) : "r"(addr));
}
__device__ __forceinline__ void mma_fp16(float* d, const uint32_t* a, uint32_t b0, uint32_t b1) {
    asm volatile("mma.sync.aligned.m16n8k16.row.col.f32.f16.f16.f32 "
        "{%0,%1,%2,%3}, {%4,%5,%6,%7}, {%8,%9}, {%0,%1,%2,%3};"
        : "+f"(d[0]), "+f"(d[1]), "+f"(d[2]), "+f"(d[3])
        : "r"(a[0]), "r"(a[1]), "r"(a[2]), "r"(a[3]), "r"(b0), "r"(b1));
}
__device__ __forceinline__ void cpasync16(uint32_t saddr, const void* g) {
    asm volatile("cp.async.cg.shared.global [%0], [%1], 16;" :: "r"(saddr), "l"(g));
}
#define CP_COMMIT() asm volatile("cp.async.commit_group;" ::: "memory")
#define CP_WAIT(n)  asm volatile("cp.async.wait_group %0;" :: "n"(n) : "memory")

__device__ __forceinline__ uint32_t pack2h(float a, float b) {
    __half ah = __float2half_rn(a);
    __half bh = __float2half_rn(b);
    return (uint32_t)(*(uint16_t*)&ah) | ((uint32_t)(*(uint16_t*)&bh) << 16);
}

// ---------------------------------------------------------------------------
// Scratch (device globals)
// ---------------------------------------------------------------------------
__device__ float g_qkv[(size_t)MROWS * NQKV];        // fp32 q|k|v projections

__device__ __half g_x16[(size_t)MROWS * H_];         // fp16 x
__device__ __half g_a16[(size_t)MROWS * H_];         // fp16 attention out
__device__ __half g_wh [(size_t)NQKV * H_];          // fp16 Wq|Wkv transposed [3072,2048]
__device__ __half g_woh[(size_t)H_ * H_];            // fp16 Wo transposed
// attention operands (fp16, single plane each)
__device__ __half g_q16[(size_t)MROWS * (NH_*D_)];
__device__ __half g_k16[(size_t)MROWS * (NKV_*D_)];
__device__ __half g_v16[(size_t)MROWS * (NKV_*D_)];

// ---------------------------------------------------------------------------
// fp32 -> fp16 (row-major). 8 elems/thread.
// ---------------------------------------------------------------------------
__global__ void tofp16_kernel(const float* __restrict__ in,
                              __half* __restrict__ o, int n8)
{
    int idx = blockIdx.x * blockDim.x + threadIdx.x;
    if (idx >= n8) return;
    union { __half b[8]; uint4 u; } uh;
    const float4* in4 = (const float4*)in;
#pragma unroll
    for (int q = 0; q < 2; q++) {
        float4 v = in4[idx * 2 + q];
        uh.b[q * 4 + 0] = __float2half_rn(v.x);
        uh.b[q * 4 + 1] = __float2half_rn(v.y);
        uh.b[q * 4 + 2] = __float2half_rn(v.z);
        uh.b[q * 4 + 3] = __float2half_rn(v.w);
    }
    ((uint4*)o)[idx] = uh.u;
}

// ---------------------------------------------------------------------------
// transpose + fp16: W[K,N] fp32 -> T[N,K] fp16. 32x32 smem tiles.
// ---------------------------------------------------------------------------
__global__ void splitT_kernel(const float* __restrict__ W,
                              __half* __restrict__ T, int K, int N)
{
    __shared__ float s[32][33];
    int tx = threadIdx.x, ty = threadIdx.y;           // (32, 8)
    int n0 = blockIdx.x * 32, k0 = blockIdx.y * 32;
#pragma unroll
    for (int i = 0; i < 4; i++) {
        int k = k0 + ty + i * 8;
        s[ty + i * 8][tx] = W[(size_t)k * N + n0 + tx];
    }
    __syncthreads();
#pragma unroll
    for (int i = 0; i < 4; i++) {
        int n = n0 + ty + i * 8;
        T[(size_t)n * K + k0 + tx] = __float2half_rn(s[tx][ty + i * 8]);
    }
}

// ---------------------------------------------------------------------------
// Plain fp16 GEMM (R12-proven): C = A[M,K] @ B[N,K]^T, single MMA pass.
// ---------------------------------------------------------------------------
#define TILE_BYTES   8192
#define STAGE_BYTES  (2 * TILE_BYTES)        // A | B
#define ST_A 0
#define ST_B 8192
#define GEMM_SMEM_BYTES (2 * STAGE_BYTES)    // 32768 -> 2 CTAs/SM

__global__ __launch_bounds__(256, 2)
void gemm_mma(const __half* __restrict__ A, const __half* __restrict__ B,
              float* __restrict__ C, int M, int N, int K)
{
    extern __shared__ char smem[];
    const uint32_t sbase = smem_to_u32(smem);
    const int tid  = threadIdx.x;
    const int wid  = tid >> 5;
    const int lane = tid & 31;
    const int br = blockIdx.y * 128;
    const int bc = blockIdx.x * 128;
    const int wr = wid & 3;
    const int wc = wid >> 2;

    const int nchunks = K >> 5;

    int r0u = (2 * tid) >> 2, u0 = (2 * tid) & 3;
    int r1u = (2 * tid + 1) >> 2, u1 = (2 * tid + 1) & 3;
    uint32_t so0 = (uint32_t)(r0u * 64 + (u0 ^ ((r0u >> 1) & 3)) * 16);
    uint32_t so1 = (uint32_t)(r1u * 64 + (u1 ^ ((r1u >> 1) & 3)) * 16);

    float acc[2][8][4];
#pragma unroll
    for (int i = 0; i < 2; i++)
#pragma unroll
        for (int j = 0; j < 8; j++)
#pragma unroll
            for (int q = 0; q < 4; q++) acc[i][j][q] = 0.f;

    const int arow0 = wr * 32 + (lane & 15);
    const int arow1 = arow0 + 16;
    const int khalf = lane >> 4;

    auto issue_loads = [&](int c, int stage) {
        uint32_t sb = sbase + stage * STAGE_BYTES;
        const __half* pA = A + (size_t)br * K + c * 32;
        const __half* pB = B + (size_t)bc * K + c * 32;
        size_t g0 = (size_t)r0u * K + u0 * 8;
        size_t g1 = (size_t)r1u * K + u1 * 8;
        cpasync16(sb + ST_A + so0, pA + g0);
        cpasync16(sb + ST_A + so1, pA + g1);
        cpasync16(sb + ST_B + so0, pB + g0);
        cpasync16(sb + ST_B + so1, pB + g1);
    };

    issue_loads(0, 0);
    CP_COMMIT();

    for (int c = 0; c < nchunks; c++) {
        if (c + 1 < nchunks) {
            issue_loads(c + 1, (c + 1) & 1);
            CP_COMMIT();
            CP_WAIT(1);
        } else {
            CP_WAIT(0);
        }
        __syncthreads();

        uint32_t sA = sbase + (c & 1) * STAGE_BYTES;

#pragma unroll
        for (int kk = 0; kk < 2; kk++) {
            uint32_t ah[2][4];
#pragma unroll
            for (int mt = 0; mt < 2; mt++) {
                int row = (mt ? arow1 : arow0);
                int cc  = (kk * 2 + khalf) ^ ((row >> 1) & 3);
                ldsm4(ah[mt], sA + ST_A + (uint32_t)(row * 64 + cc * 16));
            }
#pragma unroll
            for (int ng = 0; ng < 4; ng++) {
                int row = wc * 64 + ng * 16 + (lane & 15);
                int cc  = (kk * 2 + khalf) ^ ((row >> 1) & 3);
                uint32_t bh[4];
                ldsm4(bh, sA + ST_B + (uint32_t)(row * 64 + cc * 16));
#pragma unroll
                for (int hf = 0; hf < 2; hf++) {
                    int j = 2 * ng + hf;
                    mma_fp16(acc[0][j], ah[0], bh[hf], bh[2 + hf]);
                    mma_fp16(acc[1][j], ah[1], bh[hf], bh[2 + hf]);
                }
            }
        }
        __syncthreads();
    }

#pragma unroll
    for (int mt = 0; mt < 2; mt++) {
        int row = br + wr * 32 + mt * 16 + (lane >> 2);
#pragma unroll
        for (int j = 0; j < 8; j++) {
            int col = bc + wc * 64 + j * 8 + (lane & 3) * 2;
            *(float2*)(C + (size_t)row * N + col) =
                make_float2(acc[mt][j][0], acc[mt][j][1]);
            *(float2*)(C + (size_t)(row + 8) * N + col) =
                make_float2(acc[mt][j][2], acc[mt][j][3]);
        }
    }
}

// ---------------------------------------------------------------------------
// RoPE -> fp16 single plane (scale folded for Q).
// ---------------------------------------------------------------------------
__global__ void rope_fp16_kernel(const float* __restrict__ buf, int nheads, int ld,
                                 const float* __restrict__ cosT,
                                 const float* __restrict__ sinT,
                                 __half* __restrict__ o16,
                                 float scale, int total)
{
    int idx = blockIdx.x * blockDim.x + threadIdx.x;
    if (idx >= total) return;
    int d2 = idx & 31;
    int h  = (idx >> 5) % nheads;
    int bs = idx / (32 * nheads);
    int s  = bs & (S_ - 1);
    int d  = d2 * 2;
    const float* p = buf + (size_t)bs * ld + h * D_;
    float x1a = p[d],      x1b = p[d + 1];
    float x2a = p[d + 64], x2b = p[d + 65];
    float ca = cosT[s * D_ + d], cb = cosT[s * D_ + d + 1];
    float sa = sinT[s * D_ + d], sb = sinT[s * D_ + d + 1];
    float o1a = (x1a * ca - x2a * sa) * scale;
    float o1b = (x1b * cb - x2b * sb) * scale;
    float o2a = (x2a * ca + x1a * sa) * scale;
    float o2b = (x2b * cb + x1b * sb) * scale;
    size_t ob = (size_t)bs * (nheads * D_) + h * D_;
    *(uint32_t*)(o16 + ob + d)      = pack2h(o1a, o1b);
    *(uint32_t*)(o16 + ob + d + 64) = pack2h(o2a, o2b);
}

// V: g_qkv cols [2560,3072) -> fp16 [4096][512]
__global__ void vto16_kernel(const float* __restrict__ qkv,
                             __half* __restrict__ v16)
{
    int idx = blockIdx.x * blockDim.x + threadIdx.x;   // 4096*64
    int u8 = idx & 63;
    int r  = idx >> 6;
    const float* src = qkv + (size_t)r * NQKV + 2560 + u8 * 8;
    union { __half b[8]; uint4 u; } uh;
#pragma unroll
    for (int q = 0; q < 2; q++) {
        float4 v = *(const float4*)(src + q * 4);
        uh.b[q * 4 + 0] = __float2half_rn(v.x);
        uh.b[q * 4 + 1] = __float2half_rn(v.y);
        uh.b[q * 4 + 2] = __float2half_rn(v.z);
        uh.b[q * 4 + 3] = __float2half_rn(v.w);
    }
    *(uint4*)(v16 + (size_t)r * 512 + u8 * 8) = uh.u;
}

// ---------------------------------------------------------------------------
// Tensor-core flash attention, fp16 single-pass QK and PV.
// smem: Q persistent (32KB) + 2 stages x (K|V) (32KB each) = 96KB.
// ---------------------------------------------------------------------------
#define A_SQ  0
#define A_SKV 32768
#define A_STAGE 32768
#define ATT_SMEM_BYTES (32768 + 2*32768)   // 98304

__global__ __launch_bounds__(256, 1)
void attn_tc(const __half* __restrict__ q16,
             const __half* __restrict__ k16,
             const __half* __restrict__ v16,
             __half* __restrict__ O16,
             const int* __restrict__ seqlen)
{
    extern __shared__ char smem[];
    const uint32_t sb = smem_to_u32(smem);
    const int tid  = threadIdx.x;
    const int wid  = tid >> 5;
    const int lane = tid & 31;
    const int bh = blockIdx.x;                 // 0..31
    const int qt = 15 - blockIdx.y;            // heavy tiles first
    const int b   = bh >> 4;
    const int h   = bh & 15;
    const int kvh = h >> 2;
    const int q0  = qt * 128;
    const int len = seqlen[b];

    // ---- load Q tile (single plane), 128 rows x 16 units ----
    {
        const __half* qp = q16 + (size_t)(b * S_ + q0) * (NH_*D_) + h * D_;
#pragma unroll
        for (int i = 0; i < 8; i++) {
            int g = i * 256 + tid;
            int r = g >> 4, u = g & 15;
            uint32_t so = (uint32_t)(r * 256 + ((u ^ (r & 7)) * 16));
            cpasync16(sb + A_SQ + so, qp + (size_t)r * (NH_*D_) + u * 8);
        }
    }

    const int e  = min(q0 + 128, len);
    const int nt = (e + 63) >> 6;

    auto load_kv = [&](int t, int stage) {
        uint32_t st = sb + A_SKV + stage * A_STAGE;
        size_t base = (size_t)(b * S_ + t * 64) * (NKV_*D_) + kvh * D_;
#pragma unroll
        for (int i = 0; i < 4; i++) {
            int g = i * 256 + tid;
            int r = g >> 4, u = g & 15;
            uint32_t so = (uint32_t)(r * 256 + ((u ^ (r & 7)) * 16));
            size_t go = base + (size_t)r * (NKV_*D_) + u * 8;
            cpasync16(st + so,         k16 + go);
            cpasync16(st + 16384 + so, v16 + go);
        }
    };

    load_kv(0, 0);
    CP_COMMIT();

    float out[16][4];
#pragma unroll
    for (int j = 0; j < 16; j++)
#pragma unroll
        for (int q = 0; q < 4; q++) out[j][q] = 0.f;
    float m0 = -1e30f, m1 = -1e30f, l0 = 0.f, l1 = 0.f;

    const int wrow = q0 + wid * 16;            // warp's first q row (global)

    for (int t = 0; t < nt; t++) {
        if (t + 1 < nt) { load_kv(t + 1, (t + 1) & 1); CP_COMMIT(); CP_WAIT(1); }
        else            { CP_WAIT(0); }
        __syncthreads();

        const int k0 = t * 64;
        if (k0 <= wrow + 15) {                 // warp has at least one unmasked row
            uint32_t sK = sb + A_SKV + (t & 1) * A_STAGE;
            uint32_t sV = sK + 16384;

            // ---- scores S = Q K^T (m16 x 64), single pass ----
            float s[8][4];
#pragma unroll
            for (int j = 0; j < 8; j++)
#pragma unroll
                for (int q = 0; q < 4; q++) s[j][q] = 0.f;

#pragma unroll
            for (int kk = 0; kk < 8; kk++) {
                int ar = wid * 16 + (lane & 15);
                int au = 2 * kk + (lane >> 4);
                uint32_t aso = (uint32_t)(ar * 256 + ((au ^ (ar & 7)) * 16));
                uint32_t ah[4];
                ldsm4(ah, sb + A_SQ + aso);
#pragma unroll
                for (int ng = 0; ng < 4; ng++) {
                    int br = ng * 16 + (lane & 15);
                    uint32_t bso = (uint32_t)(br * 256 + ((au ^ (br & 7)) * 16));
                    uint32_t bk[4];
                    ldsm4(bk, sK + bso);
#pragma unroll
                    for (int hf = 0; hf < 2; hf++) {
                        int j = 2 * ng + hf;
                        mma_fp16(s[j], ah, bk[hf], bk[2 + hf]);
                    }
                }
            }

            // ---- mask ----
            const int qr0 = wrow + (lane >> 2);
            bool fullvalid = (k0 + 63 <= wrow) && (k0 + 63 < len);
            if (!fullvalid) {
#pragma unroll
                for (int j = 0; j < 8; j++) {
                    int kgb = k0 + j * 8 + (lane & 3) * 2;
#pragma unroll
                    for (int q = 0; q < 4; q++) {
                        int kg = kgb + (q & 1);
                        int qg = qr0 + ((q >> 1) << 3);
                        if (kg > qg || kg >= len) s[j][q] = -1e30f;
                    }
                }
            }

            // ---- online softmax ----
            float mx0 = -1e30f, mx1 = -1e30f;
#pragma unroll
            for (int j = 0; j < 8; j++) {
                mx0 = fmaxf(mx0, fmaxf(s[j][0], s[j][1]));
                mx1 = fmaxf(mx1, fmaxf(s[j][2], s[j][3]));
            }
#pragma unroll
            for (int off = 1; off <= 2; off <<= 1) {
                mx0 = fmaxf(mx0, __shfl_xor_sync(0xffffffffu, mx0, off));
                mx1 = fmaxf(mx1, __shfl_xor_sync(0xffffffffu, mx1, off));
            }
            float nm0 = fmaxf(m0, mx0), nm1 = fmaxf(m1, mx1);
            float sc0 = __expf(m0 - nm0), sc1 = __expf(m1 - nm1);
            m0 = nm0; m1 = nm1;
            float sum0 = 0.f, sum1 = 0.f;
#pragma unroll
            for (int j = 0; j < 8; j++) {
                s[j][0] = __expf(s[j][0] - nm0);
                s[j][1] = __expf(s[j][1] - nm0);
                s[j][2] = __expf(s[j][2] - nm1);
                s[j][3] = __expf(s[j][3] - nm1);
                sum0 += s[j][0] + s[j][1];
                sum1 += s[j][2] + s[j][3];
            }
#pragma unroll
            for (int off = 1; off <= 2; off <<= 1) {
                sum0 += __shfl_xor_sync(0xffffffffu, sum0, off);
                sum1 += __shfl_xor_sync(0xffffffffu, sum1, off);
            }
            l0 = l0 * sc0 + sum0;
            l1 = l1 * sc1 + sum1;
#pragma unroll
            for (int j = 0; j < 16; j++) {
                out[j][0] *= sc0; out[j][1] *= sc0;
                out[j][2] *= sc1; out[j][3] *= sc1;
            }

            // ---- PV: out += P V, single pass ----
#pragma unroll
            for (int jk = 0; jk < 4; jk++) {
                uint32_t pf[4];
                pf[0] = pack2h(s[2*jk][0],   s[2*jk][1]);
                pf[1] = pack2h(s[2*jk][2],   s[2*jk][3]);
                pf[2] = pack2h(s[2*jk+1][0], s[2*jk+1][1]);
                pf[3] = pack2h(s[2*jk+1][2], s[2*jk+1][3]);
#pragma unroll
                for (int gn = 0; gn < 8; gn++) {
                    int vr = jk * 16 + (lane & 15);
                    int vu = 2 * gn + (lane >> 4);
                    uint32_t vso = (uint32_t)(vr * 256 + ((vu ^ (vr & 7)) * 16));
                    uint32_t vh4[4];
                    ldsm4t(vh4, sV + vso);
#pragma unroll
                    for (int hf = 0; hf < 2; hf++) {
                        int jn = 2 * gn + hf;
                        mma_fp16(out[jn], pf, vh4[2*hf], vh4[2*hf + 1]);
                    }
                }
            }
        }
        __syncthreads();
    }

    // ---- epilogue: normalize, store fp16 ----
    float i0 = 1.0f / l0, i1 = 1.0f / l1;
    size_t ro0 = (size_t)(b * S_ + wrow + (lane >> 2)) * (NH_*D_) + h * D_;
    size_t ro1 = ro0 + (size_t)8 * (NH_*D_);
#pragma unroll
    for (int jn = 0; jn < 16; jn++) {
        int col = jn * 8 + (lane & 3) * 2;
        *(uint32_t*)(O16 + ro0 + col) = pack2h(out[jn][0] * i0, out[jn][1] * i0);
        *(uint32_t*)(O16 + ro1 + col) = pack2h(out[jn][2] * i1, out[jn][3] * i1);
    }
}

// ---------------------------------------------------------------------------
// Launch
// ---------------------------------------------------------------------------
extern "C" void kernel_launch(void* const* d_in, const int* in_sizes, int n_in,
                              void* d_out, int out_size)
{
    const float* x    = (const float*)d_in[0];
    const int*   seq  = (const int*)  d_in[1];
    const float* fcos = (const float*)d_in[2];
    const float* fsin = (const float*)d_in[3];
    const float* Wq   = (const float*)d_in[4];
    const float* Wkv  = (const float*)d_in[5];
    const float* Wo   = (const float*)d_in[6];
    float* out = (float*)d_out;

    float *qkv;
    cudaGetSymbolAddress((void**)&qkv, g_qkv);
    __half *x16, *a16, *wh, *woh, *q16, *k16, *v16;
    cudaGetSymbolAddress((void**)&x16, g_x16);
    cudaGetSymbolAddress((void**)&a16, g_a16);
    cudaGetSymbolAddress((void**)&wh,  g_wh);
    cudaGetSymbolAddress((void**)&woh, g_woh);
    cudaGetSymbolAddress((void**)&q16, g_q16);
    cudaGetSymbolAddress((void**)&k16, g_k16);
    cudaGetSymbolAddress((void**)&v16, g_v16);

    cudaFuncSetAttribute(gemm_mma, cudaFuncAttributeMaxDynamicSharedMemorySize, GEMM_SMEM_BYTES);
    cudaFuncSetAttribute(attn_tc,  cudaFuncAttributeMaxDynamicSharedMemorySize, ATT_SMEM_BYTES);

    dim3 blk(256);

    // 0) preprocessing: x -> fp16; W -> fp16 transposed
    {
        int n8 = MROWS * H_ / 8;
        tofp16_kernel<<<(n8 + 255) / 256, 256>>>(x, x16, n8);
        dim3 tb(32, 8);
        splitT_kernel<<<dim3((NH_*D_)/32,    H_/32), tb>>>(Wq,  wh,                     H_, NH_*D_);
        splitT_kernel<<<dim3((2*NKV_*D_)/32, H_/32), tb>>>(Wkv, wh + (size_t)2048 * H_, H_, 2*NKV_*D_);
        splitT_kernel<<<dim3(H_/32,          H_/32), tb>>>(Wo,  woh, H_, H_);
    }

    // 1) fused QKV projection (plain fp16, single pass)
    gemm_mma<<<dim3(24, 32), blk, GEMM_SMEM_BYTES>>>(x16, wh, qkv, MROWS, NQKV, H_);

    // 2) RoPE -> fp16 single plane (Q folds softmax scale); V -> fp16
    {
        int tq = MROWS * NH_ * 32;
        int tk = MROWS * NKV_ * 32;
        rope_fp16_kernel<<<(tq + 255) / 256, 256>>>(qkv,        NH_,  NQKV, fcos, fsin, q16, QSCALE, tq);
        rope_fp16_kernel<<<(tk + 255) / 256, 256>>>(qkv + 2048, NKV_, NQKV, fcos, fsin, k16, 1.0f,   tk);
        int tv = MROWS * 64;
        vto16_kernel<<<(tv + 255) / 256, 256>>>(qkv, v16);
    }

    // 3) attention (tensor-core, fp16 single-pass, emits fp16)
    attn_tc<<<dim3(32, 16), blk, ATT_SMEM_BYTES>>>(q16, k16, v16, a16, seq);

    // 4) output projection (plain fp16, single pass)
    gemm_mma<<<dim3(16, 32), blk, GEMM_SMEM_BYTES>>>(a16, woh, out, MROWS, H_, H_);
}

// round 15
// speedup vs baseline: 2.7686x; 1.0128x over previous
#include <cuda_runtime.h>
#include <cuda_bf16.h>
#include <cuda_fp16.h>
#include <cstdint>
#include <cstddef>

// Problem constants
#define B_   2
#define S_   2048
#define H_   2048
#define NH_  16
#define NKV_ 4
#define D_   128
#define MROWS (B_*S_)          // 4096
#define NQKV 3072              // 2048 q | 512 k | 512 v
#define QSCALE 0.08838834764831845f

// ---------------------------------------------------------------------------
// PTX helpers (sm_100-safe: mma.sync / ldmatrix / cp.async only)
// ---------------------------------------------------------------------------
__device__ __forceinline__ uint32_t smem_to_u32(const void* p) {
    uint32_t a;
    asm("{ .reg .u64 t; cvta.to.shared.u64 t, %1; cvt.u32.u64 %0, t; }" : "=r"(a) : "l"(p));
    return a;
}
__device__ __forceinline__ void ldsm4(uint32_t* r, uint32_t addr) {
    asm volatile("ldmatrix.sync.aligned.m8n8.x4.shared.b16 {%0,%1,%2,%3}, [%4];"
        : "=r"(r[0]), "=r"(r[1]), "=r"(r[2]), "=r"(r[3]) : "r"(addr));
}
__device__ __forceinline__ void ldsm4t(uint32_t* r, uint32_t addr) {
    asm volatile("ldmatrix.sync.aligned.m8n8.x4.trans.shared.b16 {%0,%1,%2,%3}, [%4];"
        : "=r"(r[0]), "=r"(r[1]), "=r"(r[2]), "=r"(r[3]) : "r"(addr));
}
__device__ __forceinline__ void mma_fp16(float* d, const uint32_t* a, uint32_t b0, uint32_t b1) {
    asm volatile("mma.sync.aligned.m16n8k16.row.col.f32.f16.f16.f32 "
        "{%0,%1,%2,%3}, {%4,%5,%6,%7}, {%8,%9}, {%0,%1,%2,%3};"
        : "+f"(d[0]), "+f"(d[1]), "+f"(d[2]), "+f"(d[3])
        : "r"(a[0]), "r"(a[1]), "r"(a[2]), "r"(a[3]), "r"(b0), "r"(b1));
}
__device__ __forceinline__ void cpasync16(uint32_t saddr, const void* g) {
    asm volatile("cp.async.cg.shared.global [%0], [%1], 16;" :: "r"(saddr), "l"(g));
}
#define CP_COMMIT() asm volatile("cp.async.commit_group;" ::: "memory")
#define CP_WAIT(n)  asm volatile("cp.async.wait_group %0;" :: "n"(n) : "memory")

__device__ __forceinline__ uint32_t pack2h(float a, float b) {
    __half ah = __float2half_rn(a);
    __half bh = __float2half_rn(b);
    return (uint32_t)(*(uint16_t*)&ah) | ((uint32_t)(*(uint16_t*)&bh) << 16);
}

// ---------------------------------------------------------------------------
// Scratch (device globals)
// ---------------------------------------------------------------------------
__device__ __half g_qkv16[(size_t)MROWS * NQKV];     // fp16 q|k|v projections
__device__ __half g_x16[(size_t)MROWS * H_];         // fp16 x
__device__ __half g_a16[(size_t)MROWS * H_];         // fp16 attention out
__device__ __half g_wh [(size_t)NQKV * H_];          // fp16 Wq|Wkv transposed
__device__ __half g_woh[(size_t)H_ * H_];            // fp16 Wo transposed
__device__ __half g_q16[(size_t)MROWS * (NH_*D_)];   // RoPE'd q (scale folded)
__device__ __half g_k16[(size_t)MROWS * (NKV_*D_)];  // RoPE'd k

// ---------------------------------------------------------------------------
// fp32 -> fp16 (row-major). 8 elems/thread.
// ---------------------------------------------------------------------------
__global__ void tofp16_kernel(const float* __restrict__ in,
                              __half* __restrict__ o, int n8)
{
    int idx = blockIdx.x * blockDim.x + threadIdx.x;
    if (idx >= n8) return;
    union { __half b[8]; uint4 u; } uh;
    const float4* in4 = (const float4*)in;
#pragma unroll
    for (int q = 0; q < 2; q++) {
        float4 v = in4[idx * 2 + q];
        uh.b[q * 4 + 0] = __float2half_rn(v.x);
        uh.b[q * 4 + 1] = __float2half_rn(v.y);
        uh.b[q * 4 + 2] = __float2half_rn(v.z);
        uh.b[q * 4 + 3] = __float2half_rn(v.w);
    }
    ((uint4*)o)[idx] = uh.u;
}

// ---------------------------------------------------------------------------
// transpose + fp16: W[K,N] fp32 -> T[N,K] fp16. 32x32 smem tiles.
// ---------------------------------------------------------------------------
__global__ void splitT_kernel(const float* __restrict__ W,
                              __half* __restrict__ T, int K, int N)
{
    __shared__ float s[32][33];
    int tx = threadIdx.x, ty = threadIdx.y;           // (32, 8)
    int n0 = blockIdx.x * 32, k0 = blockIdx.y * 32;
#pragma unroll
    for (int i = 0; i < 4; i++) {
        int k = k0 + ty + i * 8;
        s[ty + i * 8][tx] = W[(size_t)k * N + n0 + tx];
    }
    __syncthreads();
#pragma unroll
    for (int i = 0; i < 4; i++) {
        int n = n0 + ty + i * 8;
        T[(size_t)n * K + k0 + tx] = __float2half_rn(s[tx][ty + i * 8]);
    }
}

// ---------------------------------------------------------------------------
// Plain fp16 GEMM (proven): C = A[M,K] @ B[N,K]^T, single MMA pass.
// HOUT: fp16 output (qkv path) vs fp32 output (final).
// ---------------------------------------------------------------------------
#define TILE_BYTES   8192
#define STAGE_BYTES  (2 * TILE_BYTES)        // A | B
#define ST_A 0
#define ST_B 8192
#define GEMM_SMEM_BYTES (2 * STAGE_BYTES)    // 32768 -> 2 CTAs/SM

template<bool HOUT>
__global__ __launch_bounds__(256, 2)
void gemm_mma(const __half* __restrict__ A, const __half* __restrict__ B,
              void* __restrict__ Cv, int M, int N, int K)
{
    extern __shared__ char smem[];
    const uint32_t sbase = smem_to_u32(smem);
    const int tid  = threadIdx.x;
    const int wid  = tid >> 5;
    const int lane = tid & 31;
    const int br = blockIdx.y * 128;
    const int bc = blockIdx.x * 128;
    const int wr = wid & 3;
    const int wc = wid >> 2;

    const int nchunks = K >> 5;

    int r0u = (2 * tid) >> 2, u0 = (2 * tid) & 3;
    int r1u = (2 * tid + 1) >> 2, u1 = (2 * tid + 1) & 3;
    uint32_t so0 = (uint32_t)(r0u * 64 + (u0 ^ ((r0u >> 1) & 3)) * 16);
    uint32_t so1 = (uint32_t)(r1u * 64 + (u1 ^ ((r1u >> 1) & 3)) * 16);

    float acc[2][8][4];
#pragma unroll
    for (int i = 0; i < 2; i++)
#pragma unroll
        for (int j = 0; j < 8; j++)
#pragma unroll
            for (int q = 0; q < 4; q++) acc[i][j][q] = 0.f;

    const int arow0 = wr * 32 + (lane & 15);
    const int arow1 = arow0 + 16;
    const int khalf = lane >> 4;

    auto issue_loads = [&](int c, int stage) {
        uint32_t sb = sbase + stage * STAGE_BYTES;
        const __half* pA = A + (size_t)br * K + c * 32;
        const __half* pB = B + (size_t)bc * K + c * 32;
        size_t g0 = (size_t)r0u * K + u0 * 8;
        size_t g1 = (size_t)r1u * K + u1 * 8;
        cpasync16(sb + ST_A + so0, pA + g0);
        cpasync16(sb + ST_A + so1, pA + g1);
        cpasync16(sb + ST_B + so0, pB + g0);
        cpasync16(sb + ST_B + so1, pB + g1);
    };

    issue_loads(0, 0);
    CP_COMMIT();

    for (int c = 0; c < nchunks; c++) {
        if (c + 1 < nchunks) {
            issue_loads(c + 1, (c + 1) & 1);
            CP_COMMIT();
            CP_WAIT(1);
        } else {
            CP_WAIT(0);
        }
        __syncthreads();

        uint32_t sA = sbase + (c & 1) * STAGE_BYTES;

#pragma unroll
        for (int kk = 0; kk < 2; kk++) {
            uint32_t ah[2][4];
#pragma unroll
            for (int mt = 0; mt < 2; mt++) {
                int row = (mt ? arow1 : arow0);
                int cc  = (kk * 2 + khalf) ^ ((row >> 1) & 3);
                ldsm4(ah[mt], sA + ST_A + (uint32_t)(row * 64 + cc * 16));
            }
#pragma unroll
            for (int ng = 0; ng < 4; ng++) {
                int row = wc * 64 + ng * 16 + (lane & 15);
                int cc  = (kk * 2 + khalf) ^ ((row >> 1) & 3);
                uint32_t bh[4];
                ldsm4(bh, sA + ST_B + (uint32_t)(row * 64 + cc * 16));
#pragma unroll
                for (int hf = 0; hf < 2; hf++) {
                    int j = 2 * ng + hf;
                    mma_fp16(acc[0][j], ah[0], bh[hf], bh[2 + hf]);
                    mma_fp16(acc[1][j], ah[1], bh[hf], bh[2 + hf]);
                }
            }
        }
        __syncthreads();
    }

#pragma unroll
    for (int mt = 0; mt < 2; mt++) {
        int row = br + wr * 32 + mt * 16 + (lane >> 2);
#pragma unroll
        for (int j = 0; j < 8; j++) {
            int col = bc + wc * 64 + j * 8 + (lane & 3) * 2;
            if (HOUT) {
                __half* C = (__half*)Cv;
                *(uint32_t*)(C + (size_t)row * N + col) =
                    pack2h(acc[mt][j][0], acc[mt][j][1]);
                *(uint32_t*)(C + (size_t)(row + 8) * N + col) =
                    pack2h(acc[mt][j][2], acc[mt][j][3]);
            } else {
                float* C = (float*)Cv;
                *(float2*)(C + (size_t)row * N + col) =
                    make_float2(acc[mt][j][0], acc[mt][j][1]);
                *(float2*)(C + (size_t)(row + 8) * N + col) =
                    make_float2(acc[mt][j][2], acc[mt][j][3]);
            }
        }
    }
}

// ---------------------------------------------------------------------------
// RoPE: fp16 in (qkv16 layout, ld=NQKV) -> fp16 single plane out.
// ---------------------------------------------------------------------------
__global__ void rope_fp16_kernel(const __half* __restrict__ buf, int nheads,
                                 const float* __restrict__ cosT,
                                 const float* __restrict__ sinT,
                                 __half* __restrict__ o16,
                                 float scale, int total)
{
    int idx = blockIdx.x * blockDim.x + threadIdx.x;
    if (idx >= total) return;
    int d2 = idx & 31;
    int h  = (idx >> 5) % nheads;
    int bs = idx / (32 * nheads);
    int s  = bs & (S_ - 1);
    int d  = d2 * 2;
    const __half* p = buf + (size_t)bs * NQKV + h * D_;
    float x1a = __half2float(p[d]),      x1b = __half2float(p[d + 1]);
    float x2a = __half2float(p[d + 64]), x2b = __half2float(p[d + 65]);
    float ca = cosT[s * D_ + d], cb = cosT[s * D_ + d + 1];
    float sa = sinT[s * D_ + d], sb = sinT[s * D_ + d + 1];
    float o1a = (x1a * ca - x2a * sa) * scale;
    float o1b = (x1b * cb - x2b * sb) * scale;
    float o2a = (x2a * ca + x1a * sa) * scale;
    float o2b = (x2b * cb + x1b * sb) * scale;
    size_t ob = (size_t)bs * (nheads * D_) + h * D_;
    *(uint32_t*)(o16 + ob + d)      = pack2h(o1a, o1b);
    *(uint32_t*)(o16 + ob + d + 64) = pack2h(o2a, o2b);
}

// ---------------------------------------------------------------------------
// Tensor-core flash attention, fp16 single-pass, K-chunk = 128.
// V is read DIRECTLY from qkv16 (row stride NQKV, col offset 2560).
// smem: Q persistent (32KB) + 2 stages x (K 32KB | V 32KB) = 160KB.
// ---------------------------------------------------------------------------
#define A_SQ  0
#define A_SKV 32768
#define A_STAGE 65536
#define ATT_SMEM_BYTES (32768 + 2*65536)   // 163840

__global__ __launch_bounds__(256, 1)
void attn_tc(const __half* __restrict__ q16,
             const __half* __restrict__ k16,
             const __half* __restrict__ qkv16,
             __half* __restrict__ O16,
             const int* __restrict__ seqlen)
{
    extern __shared__ char smem[];
    const uint32_t sb = smem_to_u32(smem);
    const int tid  = threadIdx.x;
    const int wid  = tid >> 5;
    const int lane = tid & 31;
    const int bh = blockIdx.x;                 // 0..31
    const int qt = 15 - blockIdx.y;            // heavy tiles first
    const int b   = bh >> 4;
    const int h   = bh & 15;
    const int kvh = h >> 2;
    const int q0  = qt * 128;
    const int len = seqlen[b];

    // ---- load Q tile (single plane), 128 rows x 16 units ----
    {
        const __half* qp = q16 + (size_t)(b * S_ + q0) * (NH_*D_) + h * D_;
#pragma unroll
        for (int i = 0; i < 8; i++) {
            int g = i * 256 + tid;
            int r = g >> 4, u = g & 15;
            uint32_t so = (uint32_t)(r * 256 + ((u ^ (r & 7)) * 16));
            cpasync16(sb + A_SQ + so, qp + (size_t)r * (NH_*D_) + u * 8);
        }
    }

    const int e  = min(q0 + 128, len);
    const int nt = (e + 127) >> 7;

    auto load_kv = [&](int t, int stage) {
        uint32_t st = sb + A_SKV + stage * A_STAGE;
        const __half* kp = k16   + (size_t)(b * S_ + t * 128) * (NKV_*D_) + kvh * D_;
        const __half* vp = qkv16 + (size_t)(b * S_ + t * 128) * NQKV + 2560 + kvh * D_;
#pragma unroll
        for (int i = 0; i < 8; i++) {
            int g = i * 256 + tid;
            int r = g >> 4, u = g & 15;
            uint32_t so = (uint32_t)(r * 256 + ((u ^ (r & 7)) * 16));
            cpasync16(st + so,         kp + (size_t)r * (NKV_*D_) + u * 8);
            cpasync16(st + 32768 + so, vp + (size_t)r * NQKV + u * 8);
        }
    };

    load_kv(0, 0);
    CP_COMMIT();

    float out[16][4];
#pragma unroll
    for (int j = 0; j < 16; j++)
#pragma unroll
        for (int q = 0; q < 4; q++) out[j][q] = 0.f;
    float m0 = -1e30f, m1 = -1e30f, l0 = 0.f, l1 = 0.f;

    const int wrow = q0 + wid * 16;            // warp's first q row (global)

    for (int t = 0; t < nt; t++) {
        if (t + 1 < nt) { load_kv(t + 1, (t + 1) & 1); CP_COMMIT(); CP_WAIT(1); }
        else            { CP_WAIT(0); }
        __syncthreads();

        const int k0 = t * 128;
        if (k0 <= wrow + 15) {                 // warp has at least one unmasked row
            uint32_t sK = sb + A_SKV + (t & 1) * A_STAGE;
            uint32_t sV = sK + 32768;

            // ---- scores S = Q K^T (m16 x 128), single pass ----
            float s[16][4];
#pragma unroll
            for (int j = 0; j < 16; j++)
#pragma unroll
                for (int q = 0; q < 4; q++) s[j][q] = 0.f;

#pragma unroll
            for (int kk = 0; kk < 8; kk++) {
                int ar = wid * 16 + (lane & 15);
                int au = 2 * kk + (lane >> 4);
                uint32_t aso = (uint32_t)(ar * 256 + ((au ^ (ar & 7)) * 16));
                uint32_t ah[4];
                ldsm4(ah, sb + A_SQ + aso);
#pragma unroll
                for (int ng = 0; ng < 8; ng++) {
                    int br = ng * 16 + (lane & 15);
                    uint32_t bso = (uint32_t)(br * 256 + ((au ^ (br & 7)) * 16));
                    uint32_t bk[4];
                    ldsm4(bk, sK + bso);
#pragma unroll
                    for (int hf = 0; hf < 2; hf++) {
                        int j = 2 * ng + hf;
                        mma_fp16(s[j], ah, bk[hf], bk[2 + hf]);
                    }
                }
            }

            // ---- mask ----
            const int qr0 = wrow + (lane >> 2);
            bool fullvalid = (k0 + 127 <= wrow) && (k0 + 127 < len);
            if (!fullvalid) {
#pragma unroll
                for (int j = 0; j < 16; j++) {
                    int kgb = k0 + j * 8 + (lane & 3) * 2;
#pragma unroll
                    for (int q = 0; q < 4; q++) {
                        int kg = kgb + (q & 1);
                        int qg = qr0 + ((q >> 1) << 3);
                        if (kg > qg || kg >= len) s[j][q] = -1e30f;
                    }
                }
            }

            // ---- online softmax ----
            float mx0 = -1e30f, mx1 = -1e30f;
#pragma unroll
            for (int j = 0; j < 16; j++) {
                mx0 = fmaxf(mx0, fmaxf(s[j][0], s[j][1]));
                mx1 = fmaxf(mx1, fmaxf(s[j][2], s[j][3]));
            }
#pragma unroll
            for (int off = 1; off <= 2; off <<= 1) {
                mx0 = fmaxf(mx0, __shfl_xor_sync(0xffffffffu, mx0, off));
                mx1 = fmaxf(mx1, __shfl_xor_sync(0xffffffffu, mx1, off));
            }
            float nm0 = fmaxf(m0, mx0), nm1 = fmaxf(m1, mx1);
            float sc0 = __expf(m0 - nm0), sc1 = __expf(m1 - nm1);
            bool need = (nm0 > m0) || (nm1 > m1);
            m0 = nm0; m1 = nm1;
            float sum0 = 0.f, sum1 = 0.f;
#pragma unroll
            for (int j = 0; j < 16; j++) {
                s[j][0] = __expf(s[j][0] - nm0);
                s[j][1] = __expf(s[j][1] - nm0);
                s[j][2] = __expf(s[j][2] - nm1);
                s[j][3] = __expf(s[j][3] - nm1);
                sum0 += s[j][0] + s[j][1];
                sum1 += s[j][2] + s[j][3];
            }
#pragma unroll
            for (int off = 1; off <= 2; off <<= 1) {
                sum0 += __shfl_xor_sync(0xffffffffu, sum0, off);
                sum1 += __shfl_xor_sync(0xffffffffu, sum1, off);
            }
            l0 = l0 * sc0 + sum0;
            l1 = l1 * sc1 + sum1;
            if (__any_sync(0xffffffffu, need) && t > 0) {
#pragma unroll
                for (int j = 0; j < 16; j++) {
                    out[j][0] *= sc0; out[j][1] *= sc0;
                    out[j][2] *= sc1; out[j][3] *= sc1;
                }
            }

            // ---- PV: out += P V, single pass ----
#pragma unroll
            for (int jk = 0; jk < 8; jk++) {
                uint32_t pf[4];
                pf[0] = pack2h(s[2*jk][0],   s[2*jk][1]);
                pf[1] = pack2h(s[2*jk][2],   s[2*jk][3]);
                pf[2] = pack2h(s[2*jk+1][0], s[2*jk+1][1]);
                pf[3] = pack2h(s[2*jk+1][2], s[2*jk+1][3]);
#pragma unroll
                for (int gn = 0; gn < 8; gn++) {
                    int vr = jk * 16 + (lane & 15);
                    int vu = 2 * gn + (lane >> 4);
                    uint32_t vso = (uint32_t)(vr * 256 + ((vu ^ (vr & 7)) * 16));
                    uint32_t vh4[4];
                    ldsm4t(vh4, sV + vso);
#pragma unroll
                    for (int hf = 0; hf < 2; hf++) {
                        int jn = 2 * gn + hf;
                        mma_fp16(out[jn], pf, vh4[2*hf], vh4[2*hf + 1]);
                    }
                }
            }
        }
        __syncthreads();
    }

    // ---- epilogue: normalize, store fp16 ----
    float i0 = 1.0f / l0, i1 = 1.0f / l1;
    size_t ro0 = (size_t)(b * S_ + wrow + (lane >> 2)) * (NH_*D_) + h * D_;
    size_t ro1 = ro0 + (size_t)8 * (NH_*D_);
#pragma unroll
    for (int jn = 0; jn < 16; jn++) {
        int col = jn * 8 + (lane & 3) * 2;
        *(uint32_t*)(O16 + ro0 + col) = pack2h(out[jn][0] * i0, out[jn][1] * i0);
        *(uint32_t*)(O16 + ro1 + col) = pack2h(out[jn][2] * i1, out[jn][3] * i1);
    }
}

// ---------------------------------------------------------------------------
// Launch
// ---------------------------------------------------------------------------
extern "C" void kernel_launch(void* const* d_in, const int* in_sizes, int n_in,
                              void* d_out, int out_size)
{
    const float* x    = (const float*)d_in[0];
    const int*   seq  = (const int*)  d_in[1];
    const float* fcos = (const float*)d_in[2];
    const float* fsin = (const float*)d_in[3];
    const float* Wq   = (const float*)d_in[4];
    const float* Wkv  = (const float*)d_in[5];
    const float* Wo   = (const float*)d_in[6];
    float* out = (float*)d_out;

    __half *qkv16, *x16, *a16, *wh, *woh, *q16, *k16;
    cudaGetSymbolAddress((void**)&qkv16, g_qkv16);
    cudaGetSymbolAddress((void**)&x16, g_x16);
    cudaGetSymbolAddress((void**)&a16, g_a16);
    cudaGetSymbolAddress((void**)&wh,  g_wh);
    cudaGetSymbolAddress((void**)&woh, g_woh);
    cudaGetSymbolAddress((void**)&q16, g_q16);
    cudaGetSymbolAddress((void**)&k16, g_k16);

    cudaFuncSetAttribute(gemm_mma<true>,  cudaFuncAttributeMaxDynamicSharedMemorySize, GEMM_SMEM_BYTES);
    cudaFuncSetAttribute(gemm_mma<false>, cudaFuncAttributeMaxDynamicSharedMemorySize, GEMM_SMEM_BYTES);
    cudaFuncSetAttribute(attn_tc, cudaFuncAttributeMaxDynamicSharedMemorySize, ATT_SMEM_BYTES);

    dim3 blk(256);

    // 0) preprocessing: x -> fp16; W -> fp16 transposed
    {
        int n8 = MROWS * H_ / 8;
        tofp16_kernel<<<(n8 + 255) / 256, 256>>>(x, x16, n8);
        dim3 tb(32, 8);
        splitT_kernel<<<dim3((NH_*D_)/32,    H_/32), tb>>>(Wq,  wh,                     H_, NH_*D_);
        splitT_kernel<<<dim3((2*NKV_*D_)/32, H_/32), tb>>>(Wkv, wh + (size_t)2048 * H_, H_, 2*NKV_*D_);
        splitT_kernel<<<dim3(H_/32,          H_/32), tb>>>(Wo,  woh, H_, H_);
    }

    // 1) fused QKV projection -> fp16 output
    gemm_mma<true><<<dim3(24, 32), blk, GEMM_SMEM_BYTES>>>(x16, wh, qkv16, MROWS, NQKV, H_);

    // 2) RoPE -> fp16 single plane (Q folds softmax scale; K plain)
    {
        int tq = MROWS * NH_ * 32;
        int tk = MROWS * NKV_ * 32;
        rope_fp16_kernel<<<(tq + 255) / 256, 256>>>(qkv16,        NH_,  fcos, fsin, q16, QSCALE, tq);
        rope_fp16_kernel<<<(tk + 255) / 256, 256>>>(qkv16 + 2048, NKV_, fcos, fsin, k16, 1.0f,   tk);
    }

    // 3) attention (fp16 single-pass, 128-key chunks, V direct from qkv16)
    attn_tc<<<dim3(32, 16), blk, ATT_SMEM_BYTES>>>(q16, k16, qkv16, a16, seq);

    // 4) output projection (fp32 output)
    gemm_mma<false><<<dim3(16, 32), blk, GEMM_SMEM_BYTES>>>(a16, woh, out, MROWS, H_, H_);
}